// round 12
// baseline (speedup 1.0000x reference)
#include <cuda_runtime.h>
#include <cuda_fp16.h>
#include <cstdint>

#define SQ     4096
#define SKV    1024
#define QD     1024
#define CD     768
#define NHEADS 8
#define DHEAD  64
#define INNER  512
#define BMAX   4

// ---------------- scratch ----------------------------------------------------
__device__ __half g_qs[(size_t)BMAX * SQ * INNER];
__device__ __half g_ks[(size_t)BMAX * SKV * INNER];
__device__ __half g_vs[(size_t)BMAX * SKV * INNER];
__device__ __half g_xh[(size_t)BMAX * SQ * QD];
__device__ __half g_ch[(size_t)BMAX * SKV * CD];
__device__ __half g_ah[(size_t)BMAX * SQ * INNER];
__device__ __half g_wqh[(size_t)INNER * QD];
__device__ __half g_wkvh[(size_t)2 * INNER * CD];
__device__ __half g_woh[(size_t)QD * INNER];

// ---------------- sync state -------------------------------------------------
#define NRB (BMAX * SQ / 128)                 // 128 row blocks
__device__ int g_work;
__device__ int g_conv;
__device__ int g_kv[BMAX];
__device__ int g_qflag[NRB * 4];
__device__ int g_attn[NRB];

// ---------------- helpers ----------------------------------------------------
__device__ __forceinline__ uint32_t smem_u32(const void* p) {
    uint32_t a;
    asm("{ .reg .u64 t; cvta.to.shared.u64 t, %1; cvt.u32.u64 %0, t; }" : "=r"(a) : "l"(p));
    return a;
}
__device__ __forceinline__ void cp16(uint32_t dst, const void* src) {
    asm volatile("cp.async.cg.shared.global [%0], [%1], 16;" :: "r"(dst), "l"(src) : "memory");
}
__device__ __forceinline__ void cp_commit() {
    asm volatile("cp.async.commit_group;" ::: "memory");
}
template<int N> __device__ __forceinline__ void cp_wait() {
    asm volatile("cp.async.wait_group %0;" :: "n"(N) : "memory");
}
__device__ __forceinline__ void ldm4(uint32_t* r, uint32_t a) {
    asm volatile("ldmatrix.sync.aligned.m8n8.x4.shared.b16 {%0,%1,%2,%3}, [%4];"
                 : "=r"(r[0]), "=r"(r[1]), "=r"(r[2]), "=r"(r[3]) : "r"(a));
}
__device__ __forceinline__ void ldm4t(uint32_t* r, uint32_t a) {
    asm volatile("ldmatrix.sync.aligned.m8n8.x4.trans.shared.b16 {%0,%1,%2,%3}, [%4];"
                 : "=r"(r[0]), "=r"(r[1]), "=r"(r[2]), "=r"(r[3]) : "r"(a));
}
__device__ __forceinline__ void mma16816(float* c, const uint32_t* a, uint32_t b0, uint32_t b1) {
    asm volatile(
        "mma.sync.aligned.m16n8k16.row.col.f32.f16.f16.f32 "
        "{%0,%1,%2,%3}, {%4,%5,%6,%7}, {%8,%9}, {%0,%1,%2,%3};"
        : "+f"(c[0]), "+f"(c[1]), "+f"(c[2]), "+f"(c[3])
        : "r"(a[0]), "r"(a[1]), "r"(a[2]), "r"(a[3]), "r"(b0), "r"(b1));
}
__device__ __forceinline__ uint32_t pk2h(float lo, float hi) {
    __half2 h = __floats2half2_rn(lo, hi);
    return *reinterpret_cast<uint32_t*>(&h);
}
__device__ __forceinline__ uint32_t ex2h2(uint32_t x) {
    uint32_t r;
    asm("ex2.approx.f16x2 %0, %1;" : "=r"(r) : "r"(x));
    return r;
}
__device__ __forceinline__ uint32_t swz128(uint32_t off) { return off ^ ((off >> 3) & 0x70); }

__device__ __forceinline__ int ldacq(const int* p) {
    int v;
    asm volatile("ld.acquire.gpu.global.b32 %0, [%1];" : "=r"(v) : "l"(p) : "memory");
    return v;
}
__device__ __forceinline__ void red_rel(int* p, int v) {
    asm volatile("red.release.gpu.global.add.s32 [%0], %1;" :: "l"(p), "r"(v) : "memory");
}
// thread 0 spins until *p >= tgt, then whole CTA proceeds
__device__ __forceinline__ void wait_ge(const int* p, int tgt) {
    if (threadIdx.x == 0) {
        while (ldacq(p) < tgt) __nanosleep(64);
    }
    __syncthreads();
}

#define ONESH2 0x3C003C00u

// ---------------------------------------------------------------------------
// GEMM core (unchanged math from R11).
// ---------------------------------------------------------------------------
#define STAGES 3
#define STG_BYTES 32768
#define GEMM_SMEM (STAGES * STG_BYTES)           // 98304
#define TOTAL_SMEM (GEMM_SMEM + 16)

__device__ __forceinline__ void gemm_core(
    const __half* __restrict__ A, const __half* __restrict__ Bm,
    float* __restrict__ C, const float* __restrict__ bias,
    __half* __restrict__ outS, __half* __restrict__ outS2,
    float scale, int N, int Kreal, int bx, int by, char* smem)
{
    const uint32_t sb = smem_u32(smem);
    const int tid = threadIdx.x;
    const int lane = tid & 31;
    const int wid = tid >> 5;
    const int m0 = by << 7;
    const int n0 = bx << 7;
    const int nK = Kreal >> 6;
    const int wm = (wid >> 1) << 5;
    const int wn = (wid & 1) << 6;

    const __half* Ag = A + (size_t)m0 * Kreal;
    const __half* Bg = Bm + (size_t)n0 * Kreal;

    auto load_stage = [&](int kc) {
        const int st = kc % STAGES;
        const uint32_t sa = sb + st * STG_BYTES;
        const uint32_t sbs = sa + 16384;
        const int kb = kc << 6;
#pragma unroll
        for (int i = 0; i < 4; i++) {
            int cid = tid + (i << 8);
            int r = cid >> 3, c8 = cid & 7;
            uint32_t d = swz128((r << 7) + (c8 << 4));
            cp16(sa + d, Ag + (size_t)r * Kreal + kb + (c8 << 3));
            cp16(sbs + d, Bg + (size_t)r * Kreal + kb + (c8 << 3));
        }
        cp_commit();
    };

    float acc[2][8][4];
#pragma unroll
    for (int mi = 0; mi < 2; mi++)
#pragma unroll
        for (int ni = 0; ni < 8; ni++)
#pragma unroll
            for (int j = 0; j < 4; j++) acc[mi][ni][j] = 0.f;

    load_stage(0);
    load_stage(1);

    const uint32_t a_row = wm + (lane & 15);
    const uint32_t a_colb = (lane >> 4) << 4;
    const int q = lane >> 3;
    const uint32_t b_row = wn + ((q >> 1) << 3) + (lane & 7);
    const uint32_t b_colb = (q & 1) << 4;

    for (int kc = 0; kc < nK; kc++) {
        if (kc + 1 < nK) cp_wait<1>(); else cp_wait<0>();
        __syncthreads();
        if (kc + 2 < nK) load_stage(kc + 2);

        const uint32_t sa = sb + (kc % STAGES) * STG_BYTES;
        const uint32_t sbs = sa + 16384;

#pragma unroll
        for (int k16 = 0; k16 < 4; k16++) {
            uint32_t af[2][4];
#pragma unroll
            for (int mi = 0; mi < 2; mi++)
                ldm4(af[mi], sa + swz128(((a_row + mi * 16) << 7) + k16 * 32 + a_colb));
#pragma unroll
            for (int nj = 0; nj < 4; nj++) {
                uint32_t bf[4];
                ldm4(bf, sbs + swz128(((b_row + nj * 16) << 7) + k16 * 32 + b_colb));
#pragma unroll
                for (int mi = 0; mi < 2; mi++) {
                    mma16816(acc[mi][2 * nj],     af[mi], bf[0], bf[1]);
                    mma16816(acc[mi][2 * nj + 1], af[mi], bf[2], bf[3]);
                }
            }
        }
    }

    const int g = lane >> 2, t = lane & 3;
    if (outS2) {
        const int half_ = N >> 1;
#pragma unroll
        for (int mi = 0; mi < 2; mi++) {
#pragma unroll
            for (int ni = 0; ni < 8; ni++) {
                const int col = n0 + wn + ni * 8 + 2 * t;
                __half* base = outS;
                int c2 = col;
                if (col >= half_) { base = outS2; c2 = col - half_; }
#pragma unroll
                for (int rr = 0; rr < 2; rr++) {
                    const int row = m0 + wm + mi * 16 + g + rr * 8;
                    *(uint32_t*)&base[(size_t)row * half_ + c2] =
                        pk2h(acc[mi][ni][2 * rr], acc[mi][ni][2 * rr + 1]);
                }
            }
        }
    } else if (outS) {
#pragma unroll
        for (int mi = 0; mi < 2; mi++) {
#pragma unroll
            for (int ni = 0; ni < 8; ni++) {
                const int col = n0 + wn + ni * 8 + 2 * t;
#pragma unroll
                for (int rr = 0; rr < 2; rr++) {
                    const int row = m0 + wm + mi * 16 + g + rr * 8;
                    *(uint32_t*)&outS[(size_t)row * N + col] =
                        pk2h(acc[mi][ni][2 * rr] * scale, acc[mi][ni][2 * rr + 1] * scale);
                }
            }
        }
    } else {
#pragma unroll
        for (int mi = 0; mi < 2; mi++) {
#pragma unroll
            for (int ni = 0; ni < 8; ni++) {
                const int row = m0 + wm + mi * 16 + g;
                const int col = n0 + wn + ni * 8 + 2 * t;
                float b0 = bias[col], b1 = bias[col + 1];
                float2 v0 = make_float2(acc[mi][ni][0] + b0, acc[mi][ni][1] + b1);
                float2 v1 = make_float2(acc[mi][ni][2] + b0, acc[mi][ni][3] + b1);
                *(float2*)&C[(size_t)row * N + col] = v0;
                *(float2*)&C[(size_t)(row + 8) * N + col] = v1;
            }
        }
    }
}

// ---------------------------------------------------------------------------
// Attention core (unchanged math from R11), parameterized by (b, h, q0).
// ---------------------------------------------------------------------------
__device__ __forceinline__ void attn_core(
    const __half* __restrict__ Qs, const __half* __restrict__ Ks,
    const __half* __restrict__ Vs, __half* __restrict__ AH,
    int b, int h, int q0, char* smem)
{
    const uint32_t Qb = smem_u32(smem);
    const uint32_t KVb = Qb + 16384;
    const int tid = threadIdx.x;
    const int lane = tid & 31;
    const int wid = tid >> 5;

    const __half* Qg = Qs + ((size_t)(b * SQ + q0)) * INNER + h * 64;
    const __half* Kg = Ks + ((size_t)(b * SKV)) * INNER + h * 64;
    const __half* Vg = Vs + ((size_t)(b * SKV)) * INNER + h * 64;

#pragma unroll
    for (int i = 0; i < 4; i++) {
        int cid = (i << 8) + tid;
        int r = cid >> 3, w = cid & 7;
        uint32_t dst = Qb + (r << 7) + ((w << 4) ^ ((r & 7) << 4));
        cp16(dst, Qg + (size_t)r * INNER + w * 8);
    }
    cp_commit();

    auto load_kv = [&](int c) {
        const uint32_t st = KVb + (c & 1) * 16384;
#pragma unroll
        for (int i = 0; i < 4; i++) {
            int cid = (i << 8) + tid;
            int isV = cid >> 9;
            int l9 = cid & 511;
            int r = l9 >> 3, w = l9 & 7;
            const __half* src = (isV ? Vg : Kg) + (size_t)(c * 64 + r) * INNER + w * 8;
            uint32_t dst = st + isV * 8192 + (r << 7) + ((w << 4) ^ ((r & 7) << 4));
            cp16(dst, src);
        }
        cp_commit();
    };
    load_kv(0);
    load_kv(1);

    const int wm = wid << 4;
    const uint32_t a_row = wm + (lane & 15);
    const uint32_t a_csel = (lane >> 4) << 4;
    const int q2 = lane >> 3;
    const uint32_t b_roff = ((q2 >> 1) << 3) + (lane & 7);
    const uint32_t b_csel = (q2 & 1) << 4;
    const uint32_t v_roff = (((lane >> 3) & 1) << 3) + (lane & 7);
    const uint32_t v_csel = (lane >> 4) << 4;

    float o[8][4];
#pragma unroll
    for (int ni = 0; ni < 8; ni++)
#pragma unroll
        for (int j = 0; j < 4; j++) o[ni][j] = 0.f;
    float lacc[4] = {0.f, 0.f, 0.f, 0.f};

    for (int kc = 0; kc < SKV / 64; kc++) {
        if (kc + 1 < SKV / 64) cp_wait<1>(); else cp_wait<0>();
        __syncthreads();
        const uint32_t Kst = KVb + (kc & 1) * 16384;
        const uint32_t Vst = Kst + 8192;

        float s[8][4];
#pragma unroll
        for (int ni = 0; ni < 8; ni++)
#pragma unroll
            for (int j = 0; j < 4; j++) s[ni][j] = 0.f;

#pragma unroll
        for (int k16 = 0; k16 < 4; k16++) {
            uint32_t af[4];
            ldm4(af, Qb + swz128((a_row << 7) + k16 * 32 + a_csel));
#pragma unroll
            for (int nj = 0; nj < 4; nj++) {
                const uint32_t br = nj * 16 + b_roff;
                uint32_t bf[4];
                ldm4(bf, Kst + swz128((br << 7) + k16 * 32 + b_csel));
                mma16816(s[2 * nj],     af, bf[0], bf[1]);
                mma16816(s[2 * nj + 1], af, bf[2], bf[3]);
            }
        }

        uint32_t pf[4][4];
#pragma unroll
        for (int nj = 0; nj < 4; nj++) {
            pf[nj][0] = ex2h2(pk2h(s[2 * nj][0],     s[2 * nj][1]));
            pf[nj][1] = ex2h2(pk2h(s[2 * nj][2],     s[2 * nj][3]));
            pf[nj][2] = ex2h2(pk2h(s[2 * nj + 1][0], s[2 * nj + 1][1]));
            pf[nj][3] = ex2h2(pk2h(s[2 * nj + 1][2], s[2 * nj + 1][3]));
            mma16816(lacc, pf[nj], ONESH2, ONESH2);
        }

#pragma unroll
        for (int j = 0; j < 4; j++) {
            const uint32_t vr = j * 16 + v_roff;
#pragma unroll
            for (int u = 0; u < 4; u++) {
                uint32_t vf[4];
                ldm4t(vf, Vst + swz128((vr << 7) + u * 32 + v_csel));
                mma16816(o[2 * u],     pf[j], vf[0], vf[1]);
                mma16816(o[2 * u + 1], pf[j], vf[2], vf[3]);
            }
        }

        __syncthreads();
        if (kc + 2 < SKV / 64) load_kv(kc + 2);
    }

    const float inv0 = 1.f / lacc[0], inv1 = 1.f / lacc[2];

    const int r0 = q0 + wm + (lane >> 2);
    __half* base0 = AH + (size_t)(b * SQ + r0) * INNER + h * 64;
    __half* base1 = base0 + (size_t)8 * INNER;
#pragma unroll
    for (int ni = 0; ni < 8; ni++) {
        const int dd = ni * 8 + 2 * (lane & 3);
        *(uint32_t*)(base0 + dd) = pk2h(o[ni][0] * inv0, o[ni][1] * inv0);
        *(uint32_t*)(base1 + dd) = pk2h(o[ni][2] * inv1, o[ni][3] * inv1);
    }
}

// ---------------------------------------------------------------------------
// Counter reset (runs before the mega kernel each launch).
// ---------------------------------------------------------------------------
__global__ void reset_counters()
{
    int t = threadIdx.x;
    if (t == 0) { g_work = 0; g_conv = 0; }
    if (t < BMAX) g_kv[t] = 0;
    for (int i = t; i < NRB * 4; i += 256) g_qflag[i] = 0;
    for (int i = t; i < NRB; i += 256) g_attn[i] = 0;
}

// ---------------------------------------------------------------------------
// Persistent mega kernel: work queue over
//   [act converts | weight transposes | KV tiles | Q tiles | attention | O-proj]
// with release/acquire dependency counters. Deadlock-free: every wait targets
// strictly earlier queue entries, and claimed items are actively executed.
// ---------------------------------------------------------------------------
__global__ __launch_bounds__(256, 2)
void mega(const float* __restrict__ X, const float* __restrict__ Ctx,
          const float* __restrict__ Wq, const float* __restrict__ Wk,
          const float* __restrict__ Wv, const float* __restrict__ Wo,
          const float* __restrict__ bo, float* __restrict__ out, int B)
{
    extern __shared__ char smem[];
    int* shw = (int*)(smem + GEMM_SMEM);
    const int tid = threadIdx.x;

    __half *qs = g_qs, *ks = g_ks, *vs = g_vs, *xh = g_xh, *ch = g_ch, *ah = g_ah;
    __half *wqh = g_wqh, *wkvh = g_wkvh, *woh = g_woh;

    const int n4x = B * SQ * (QD / 4);
    const int n4c = B * SKV * (CD / 4);
    const int nActI = (n4x + n4c + 4095) >> 12;    // 4096 float4 per item
    const int cW1 = nActI + 1792;                  // conv target
    const int nKV = 8 * (B * SKV / 128);
    const int cW2 = cW1 + nKV;
    const int nQ = 4 * (B * SQ / 128);
    const int cW3 = cW2 + nQ;
    const int nAtt = (SQ / 128) * (B * NHEADS);
    const int cW4 = cW3 + nAtt;
    const int nO = (QD / 128) * (B * SQ / 128);
    const int total = cW4 + nO;
    const int kvTgt = 8 * (SKV / 128);             // 64
    const float qscale = 0.125f * 1.44269504f;

    for (;;) {
        __syncthreads();
        if (tid == 0) shw[0] = atomicAdd(&g_work, 1);
        __syncthreads();
        const int w = shw[0];
        if (w >= total) return;

        if (w < nActI) {
            // ---- activation convert item: 4096 float4s ----
            int base = (w << 12) + tid;
#pragma unroll
            for (int i = 0; i < 16; i++) {
                int idx = base + (i << 8);
                const float* src;
                __half* dst;
                int k;
                if (idx < n4x) { src = X; dst = xh; k = idx; }
                else if (idx < n4x + n4c) { src = Ctx; dst = ch; k = idx - n4x; }
                else continue;
                float4 v = ((const float4*)src)[k];
                __half hv[4];
                hv[0] = __float2half(v.x); hv[1] = __float2half(v.y);
                hv[2] = __float2half(v.z); hv[3] = __float2half(v.w);
                ((uint2*)dst)[k] = *(uint2*)hv;
            }
            __syncthreads();
            if (tid == 0) red_rel(&g_conv, 1);
        } else if (w < cW1) {
            // ---- weight transpose item ----
            int bid = w - nActI;
            const float* W;
            __half* Wt;
            int K, N, nx;
            if (bid < 512)       { W = Wq; Wt = wqh;  K = QD;   N = INNER; nx = 16; }
            else if (bid < 896)  { bid -= 512;  W = Wk; Wt = wkvh; K = CD; N = INNER; nx = 16; }
            else if (bid < 1280) { bid -= 896;  W = Wv; Wt = wkvh + (size_t)INNER * CD; K = CD; N = INNER; nx = 16; }
            else                 { bid -= 1280; W = Wo; Wt = woh;  K = INNER; N = QD;  nx = 32; }
            const int n0 = (bid % nx) << 5, k0 = (bid / nx) << 5;
            float* t = (float*)smem;                   // [32][33]
            const int tx = tid & 31, ty = tid >> 5;
#pragma unroll
            for (int i = 0; i < 4; i++)
                t[(ty + 8 * i) * 33 + tx] = W[(size_t)(k0 + ty + 8 * i) * N + n0 + tx];
            __syncthreads();
#pragma unroll
            for (int i = 0; i < 4; i++) {
                const int n = n0 + ty + 8 * i;
                const int k = k0 + tx;
                Wt[(size_t)n * K + k] = __float2half(t[tx * 33 + ty + 8 * i]);
            }
            __syncthreads();
            if (tid == 0) red_rel(&g_conv, 1);
        } else if (w < cW2) {
            // ---- KV projection tile ----
            const int j = w - cW1;
            wait_ge(&g_conv, cW1);
            gemm_core(ch, wkvh, nullptr, nullptr, ks, vs, 1.0f,
                      2 * INNER, CD, j & 7, j >> 3, smem);
            __syncthreads();
            if (tid == 0) red_rel(&g_kv[(j >> 3) >> 3], 1);
        } else if (w < cW3) {
            // ---- Q projection tile ----
            const int i = w - cW2;
            wait_ge(&g_conv, cW1);
            gemm_core(xh, wqh, nullptr, nullptr, qs, nullptr, qscale,
                      INNER, QD, i & 3, i >> 2, smem);
            __syncthreads();
            if (tid == 0) red_rel(&g_qflag[i], 1);     // flat [by*4 + bx] == i
        } else if (w < cW4) {
            // ---- attention tile ----
            const int a = w - cW3;
            const int qx = a & 31;
            const int y = a >> 5;
            const int b = y >> 3, h = y & 7;
            const int rb = b * 32 + qx;
            wait_ge(&g_kv[b], kvTgt);
            wait_ge(&g_qflag[rb * 4 + (h >> 1)], 1);
            attn_core(qs, ks, vs, ah, b, h, qx << 7, smem);
            __syncthreads();
            if (tid == 0) red_rel(&g_attn[rb], 1);
        } else {
            // ---- O projection tile ----
            const int o = w - cW4;
            const int by = o >> 3, bx = o & 7;
            wait_ge(&g_attn[by], 8);
            gemm_core(ah, woh, out, bo, nullptr, nullptr, 1.0f,
                      QD, INNER, bx, by, smem);
        }
    }
}

// ---------------------------------------------------------------------------
extern "C" void kernel_launch(void* const* d_in, const int* in_sizes, int n_in,
                              void* d_out, int out_size)
{
    const float* x   = (const float*)d_in[0];
    const float* ctx = (const float*)d_in[1];
    const float* Wq  = (const float*)d_in[2];
    const float* Wk  = (const float*)d_in[3];
    const float* Wv  = (const float*)d_in[4];
    const float* Wo  = (const float*)d_in[5];
    const float* bo  = (const float*)d_in[6];
    float* out = (float*)d_out;

    const int B = in_sizes[0] / (SQ * QD);

    cudaFuncSetAttribute(mega, cudaFuncAttributeMaxDynamicSharedMemorySize, TOTAL_SMEM);

    int sms = 148;
    cudaDeviceGetAttribute(&sms, cudaDevAttrMultiProcessorCount, 0);

    reset_counters<<<1, 256>>>();
    mega<<<2 * sms, 256, TOTAL_SMEM>>>(x, ctx, Wq, Wk, Wv, Wo, bo, out, B);
}

// round 13
// speedup vs baseline: 1.0077x; 1.0077x over previous
#include <cuda_runtime.h>
#include <cuda_fp16.h>
#include <cstdint>

#define SQ     4096
#define SKV    1024
#define QD     1024
#define CD     768
#define NHEADS 8
#define DHEAD  64
#define INNER  512
#define BMAX   4

// ---------------- scratch ----------------------------------------------------
__device__ __half g_qs[(size_t)BMAX * SQ * INNER];
__device__ __half g_ks[(size_t)BMAX * SKV * INNER];
__device__ __half g_vs[(size_t)BMAX * SKV * INNER];
__device__ __half g_xh[(size_t)BMAX * SQ * QD];
__device__ __half g_ch[(size_t)BMAX * SKV * CD];
__device__ __half g_ah[(size_t)BMAX * SQ * INNER];
__device__ __half g_wqh[(size_t)INNER * QD];
__device__ __half g_wkvh[(size_t)2 * INNER * CD];
__device__ __half g_woh[(size_t)QD * INNER];

// ---------------- sync state -------------------------------------------------
#define NRB (BMAX * SQ / 128)                 // 128 row blocks
__device__ int g_work;
__device__ int g_conv;
__device__ int g_kv[BMAX];
__device__ int g_qflag[NRB * 4];
__device__ int g_attn[NRB];

// ---------------- helpers ----------------------------------------------------
__device__ __forceinline__ uint32_t smem_u32(const void* p) {
    uint32_t a;
    asm("{ .reg .u64 t; cvta.to.shared.u64 t, %1; cvt.u32.u64 %0, t; }" : "=r"(a) : "l"(p));
    return a;
}
__device__ __forceinline__ void cp16(uint32_t dst, const void* src) {
    asm volatile("cp.async.cg.shared.global [%0], [%1], 16;" :: "r"(dst), "l"(src) : "memory");
}
__device__ __forceinline__ void cp_commit() {
    asm volatile("cp.async.commit_group;" ::: "memory");
}
template<int N> __device__ __forceinline__ void cp_wait() {
    asm volatile("cp.async.wait_group %0;" :: "n"(N) : "memory");
}
__device__ __forceinline__ void ldm4(uint32_t* r, uint32_t a) {
    asm volatile("ldmatrix.sync.aligned.m8n8.x4.shared.b16 {%0,%1,%2,%3}, [%4];"
                 : "=r"(r[0]), "=r"(r[1]), "=r"(r[2]), "=r"(r[3]) : "r"(a));
}
__device__ __forceinline__ void ldm4t(uint32_t* r, uint32_t a) {
    asm volatile("ldmatrix.sync.aligned.m8n8.x4.trans.shared.b16 {%0,%1,%2,%3}, [%4];"
                 : "=r"(r[0]), "=r"(r[1]), "=r"(r[2]), "=r"(r[3]) : "r"(a));
}
__device__ __forceinline__ void mma16816(float* c, const uint32_t* a, uint32_t b0, uint32_t b1) {
    asm volatile(
        "mma.sync.aligned.m16n8k16.row.col.f32.f16.f16.f32 "
        "{%0,%1,%2,%3}, {%4,%5,%6,%7}, {%8,%9}, {%0,%1,%2,%3};"
        : "+f"(c[0]), "+f"(c[1]), "+f"(c[2]), "+f"(c[3])
        : "r"(a[0]), "r"(a[1]), "r"(a[2]), "r"(a[3]), "r"(b0), "r"(b1));
}
__device__ __forceinline__ uint32_t pk2h(float lo, float hi) {
    __half2 h = __floats2half2_rn(lo, hi);
    return *reinterpret_cast<uint32_t*>(&h);
}
__device__ __forceinline__ uint32_t ex2h2(uint32_t x) {
    uint32_t r;
    asm("ex2.approx.f16x2 %0, %1;" : "=r"(r) : "r"(x));
    return r;
}
__device__ __forceinline__ uint32_t swz128(uint32_t off) { return off ^ ((off >> 3) & 0x70); }

__device__ __forceinline__ int ldacq(const int* p) {
    int v;
    asm volatile("ld.acquire.gpu.global.b32 %0, [%1];" : "=r"(v) : "l"(p) : "memory");
    return v;
}
__device__ __forceinline__ void red_rel(int* p, int v) {
    asm volatile("red.release.gpu.global.add.s32 [%0], %1;" :: "l"(p), "r"(v) : "memory");
}
__device__ __forceinline__ void wait_ge(const int* p, int tgt) {
    if (threadIdx.x == 0) {
        while (ldacq(p) < tgt) __nanosleep(64);
    }
    __syncthreads();
}

#define ONESH2 0x3C003C00u

// ---------------------------------------------------------------------------
// GEMM core — ONE inlined copy (single call site in mega).
// ---------------------------------------------------------------------------
#define STAGES 3
#define STG_BYTES 32768
#define GEMM_SMEM (STAGES * STG_BYTES)           // 98304
#define TOTAL_SMEM (GEMM_SMEM + 16)

__device__ __forceinline__ void gemm_core(
    const __half* __restrict__ A, const __half* __restrict__ Bm,
    float* __restrict__ C, const float* __restrict__ bias,
    __half* __restrict__ outS, __half* __restrict__ outS2,
    float scale, int N, int Kreal, int bx, int by, char* smem)
{
    const uint32_t sb = smem_u32(smem);
    const int tid = threadIdx.x;
    const int lane = tid & 31;
    const int wid = tid >> 5;
    const int m0 = by << 7;
    const int n0 = bx << 7;
    const int nK = Kreal >> 6;
    const int wm = (wid >> 1) << 5;
    const int wn = (wid & 1) << 6;

    const __half* Ag = A + (size_t)m0 * Kreal;
    const __half* Bg = Bm + (size_t)n0 * Kreal;

    auto load_stage = [&](int kc) {
        const int st = kc % STAGES;
        const uint32_t sa = sb + st * STG_BYTES;
        const uint32_t sbs = sa + 16384;
        const int kb = kc << 6;
#pragma unroll
        for (int i = 0; i < 4; i++) {
            int cid = tid + (i << 8);
            int r = cid >> 3, c8 = cid & 7;
            uint32_t d = swz128((r << 7) + (c8 << 4));
            cp16(sa + d, Ag + (size_t)r * Kreal + kb + (c8 << 3));
            cp16(sbs + d, Bg + (size_t)r * Kreal + kb + (c8 << 3));
        }
        cp_commit();
    };

    float acc[2][8][4];
#pragma unroll
    for (int mi = 0; mi < 2; mi++)
#pragma unroll
        for (int ni = 0; ni < 8; ni++)
#pragma unroll
            for (int j = 0; j < 4; j++) acc[mi][ni][j] = 0.f;

    load_stage(0);
    load_stage(1);

    const uint32_t a_row = wm + (lane & 15);
    const uint32_t a_colb = (lane >> 4) << 4;
    const int q = lane >> 3;
    const uint32_t b_row = wn + ((q >> 1) << 3) + (lane & 7);
    const uint32_t b_colb = (q & 1) << 4;

    for (int kc = 0; kc < nK; kc++) {
        if (kc + 1 < nK) cp_wait<1>(); else cp_wait<0>();
        __syncthreads();
        if (kc + 2 < nK) load_stage(kc + 2);

        const uint32_t sa = sb + (kc % STAGES) * STG_BYTES;
        const uint32_t sbs = sa + 16384;

#pragma unroll
        for (int k16 = 0; k16 < 4; k16++) {
            uint32_t af[2][4];
#pragma unroll
            for (int mi = 0; mi < 2; mi++)
                ldm4(af[mi], sa + swz128(((a_row + mi * 16) << 7) + k16 * 32 + a_colb));
#pragma unroll
            for (int nj = 0; nj < 4; nj++) {
                uint32_t bf[4];
                ldm4(bf, sbs + swz128(((b_row + nj * 16) << 7) + k16 * 32 + b_colb));
#pragma unroll
                for (int mi = 0; mi < 2; mi++) {
                    mma16816(acc[mi][2 * nj],     af[mi], bf[0], bf[1]);
                    mma16816(acc[mi][2 * nj + 1], af[mi], bf[2], bf[3]);
                }
            }
        }
    }

    const int g = lane >> 2, t = lane & 3;
    if (outS2) {
        const int half_ = N >> 1;
#pragma unroll
        for (int mi = 0; mi < 2; mi++) {
#pragma unroll
            for (int ni = 0; ni < 8; ni++) {
                const int col = n0 + wn + ni * 8 + 2 * t;
                __half* base = outS;
                int c2 = col;
                if (col >= half_) { base = outS2; c2 = col - half_; }
#pragma unroll
                for (int rr = 0; rr < 2; rr++) {
                    const int row = m0 + wm + mi * 16 + g + rr * 8;
                    *(uint32_t*)&base[(size_t)row * half_ + c2] =
                        pk2h(acc[mi][ni][2 * rr], acc[mi][ni][2 * rr + 1]);
                }
            }
        }
    } else if (outS) {
#pragma unroll
        for (int mi = 0; mi < 2; mi++) {
#pragma unroll
            for (int ni = 0; ni < 8; ni++) {
                const int col = n0 + wn + ni * 8 + 2 * t;
#pragma unroll
                for (int rr = 0; rr < 2; rr++) {
                    const int row = m0 + wm + mi * 16 + g + rr * 8;
                    *(uint32_t*)&outS[(size_t)row * N + col] =
                        pk2h(acc[mi][ni][2 * rr] * scale, acc[mi][ni][2 * rr + 1] * scale);
                }
            }
        }
    } else {
#pragma unroll
        for (int mi = 0; mi < 2; mi++) {
#pragma unroll
            for (int ni = 0; ni < 8; ni++) {
                const int row = m0 + wm + mi * 16 + g;
                const int col = n0 + wn + ni * 8 + 2 * t;
                float b0 = bias[col], b1 = bias[col + 1];
                float2 v0 = make_float2(acc[mi][ni][0] + b0, acc[mi][ni][1] + b1);
                float2 v1 = make_float2(acc[mi][ni][2] + b0, acc[mi][ni][3] + b1);
                *(float2*)&C[(size_t)row * N + col] = v0;
                *(float2*)&C[(size_t)(row + 8) * N + col] = v1;
            }
        }
    }
}

// ---------------------------------------------------------------------------
// Attention core (one call site).
// ---------------------------------------------------------------------------
__device__ __forceinline__ void attn_core(
    const __half* __restrict__ Qs, const __half* __restrict__ Ks,
    const __half* __restrict__ Vs, __half* __restrict__ AH,
    int b, int h, int q0, char* smem)
{
    const uint32_t Qb = smem_u32(smem);
    const uint32_t KVb = Qb + 16384;
    const int tid = threadIdx.x;
    const int lane = tid & 31;
    const int wid = tid >> 5;

    const __half* Qg = Qs + ((size_t)(b * SQ + q0)) * INNER + h * 64;
    const __half* Kg = Ks + ((size_t)(b * SKV)) * INNER + h * 64;
    const __half* Vg = Vs + ((size_t)(b * SKV)) * INNER + h * 64;

#pragma unroll
    for (int i = 0; i < 4; i++) {
        int cid = (i << 8) + tid;
        int r = cid >> 3, w = cid & 7;
        uint32_t dst = Qb + (r << 7) + ((w << 4) ^ ((r & 7) << 4));
        cp16(dst, Qg + (size_t)r * INNER + w * 8);
    }
    cp_commit();

    auto load_kv = [&](int c) {
        const uint32_t st = KVb + (c & 1) * 16384;
#pragma unroll
        for (int i = 0; i < 4; i++) {
            int cid = (i << 8) + tid;
            int isV = cid >> 9;
            int l9 = cid & 511;
            int r = l9 >> 3, w = l9 & 7;
            const __half* src = (isV ? Vg : Kg) + (size_t)(c * 64 + r) * INNER + w * 8;
            uint32_t dst = st + isV * 8192 + (r << 7) + ((w << 4) ^ ((r & 7) << 4));
            cp16(dst, src);
        }
        cp_commit();
    };
    load_kv(0);
    load_kv(1);

    const int wm = wid << 4;
    const uint32_t a_row = wm + (lane & 15);
    const uint32_t a_csel = (lane >> 4) << 4;
    const int q2 = lane >> 3;
    const uint32_t b_roff = ((q2 >> 1) << 3) + (lane & 7);
    const uint32_t b_csel = (q2 & 1) << 4;
    const uint32_t v_roff = (((lane >> 3) & 1) << 3) + (lane & 7);
    const uint32_t v_csel = (lane >> 4) << 4;

    float o[8][4];
#pragma unroll
    for (int ni = 0; ni < 8; ni++)
#pragma unroll
        for (int j = 0; j < 4; j++) o[ni][j] = 0.f;
    float lacc[4] = {0.f, 0.f, 0.f, 0.f};

    for (int kc = 0; kc < SKV / 64; kc++) {
        if (kc + 1 < SKV / 64) cp_wait<1>(); else cp_wait<0>();
        __syncthreads();
        const uint32_t Kst = KVb + (kc & 1) * 16384;
        const uint32_t Vst = Kst + 8192;

        float s[8][4];
#pragma unroll
        for (int ni = 0; ni < 8; ni++)
#pragma unroll
            for (int j = 0; j < 4; j++) s[ni][j] = 0.f;

#pragma unroll
        for (int k16 = 0; k16 < 4; k16++) {
            uint32_t af[4];
            ldm4(af, Qb + swz128((a_row << 7) + k16 * 32 + a_csel));
#pragma unroll
            for (int nj = 0; nj < 4; nj++) {
                const uint32_t br = nj * 16 + b_roff;
                uint32_t bf[4];
                ldm4(bf, Kst + swz128((br << 7) + k16 * 32 + b_csel));
                mma16816(s[2 * nj],     af, bf[0], bf[1]);
                mma16816(s[2 * nj + 1], af, bf[2], bf[3]);
            }
        }

        uint32_t pf[4][4];
#pragma unroll
        for (int nj = 0; nj < 4; nj++) {
            pf[nj][0] = ex2h2(pk2h(s[2 * nj][0],     s[2 * nj][1]));
            pf[nj][1] = ex2h2(pk2h(s[2 * nj][2],     s[2 * nj][3]));
            pf[nj][2] = ex2h2(pk2h(s[2 * nj + 1][0], s[2 * nj + 1][1]));
            pf[nj][3] = ex2h2(pk2h(s[2 * nj + 1][2], s[2 * nj + 1][3]));
            mma16816(lacc, pf[nj], ONESH2, ONESH2);
        }

#pragma unroll
        for (int j = 0; j < 4; j++) {
            const uint32_t vr = j * 16 + v_roff;
#pragma unroll
            for (int u = 0; u < 4; u++) {
                uint32_t vf[4];
                ldm4t(vf, Vst + swz128((vr << 7) + u * 32 + v_csel));
                mma16816(o[2 * u],     pf[j], vf[0], vf[1]);
                mma16816(o[2 * u + 1], pf[j], vf[2], vf[3]);
            }
        }

        __syncthreads();
        if (kc + 2 < SKV / 64) load_kv(kc + 2);
    }

    const float inv0 = 1.f / lacc[0], inv1 = 1.f / lacc[2];

    const int r0 = q0 + wm + (lane >> 2);
    __half* base0 = AH + (size_t)(b * SQ + r0) * INNER + h * 64;
    __half* base1 = base0 + (size_t)8 * INNER;
#pragma unroll
    for (int ni = 0; ni < 8; ni++) {
        const int dd = ni * 8 + 2 * (lane & 3);
        *(uint32_t*)(base0 + dd) = pk2h(o[ni][0] * inv0, o[ni][1] * inv0);
        *(uint32_t*)(base1 + dd) = pk2h(o[ni][2] * inv1, o[ni][3] * inv1);
    }
}

// ---------------------------------------------------------------------------
__global__ void reset_counters()
{
    int t = threadIdx.x;
    if (t == 0) { g_work = 0; g_conv = 0; }
    if (t < BMAX) g_kv[t] = 0;
    for (int i = t; i < NRB * 4; i += 256) g_qflag[i] = 0;
    for (int i = t; i < NRB; i += 256) g_attn[i] = 0;
}

// ---------------------------------------------------------------------------
// Persistent mega kernel v2. Queue:
//   [act converts | weight transposes | KV | Q | attention (b,qx,h) | O (rb,bx)]
// Single gemm_core call site (one code copy); attention row-blocks complete
// consecutively so O-proj spins are ~zero.
// ---------------------------------------------------------------------------
__global__ __launch_bounds__(256, 2)
void mega(const float* __restrict__ X, const float* __restrict__ Ctx,
          const float* __restrict__ Wq, const float* __restrict__ Wk,
          const float* __restrict__ Wv, const float* __restrict__ Wo,
          const float* __restrict__ bo, float* __restrict__ out, int B)
{
    extern __shared__ char smem[];
    int* shw = (int*)(smem + GEMM_SMEM);
    const int tid = threadIdx.x;

    __half *qs = g_qs, *ks = g_ks, *vs = g_vs, *xh = g_xh, *ch = g_ch, *ah = g_ah;
    __half *wqh = g_wqh, *wkvh = g_wkvh, *woh = g_woh;

    const int n4x = B * SQ * (QD / 4);
    const int n4c = B * SKV * (CD / 4);
    const int nActI = (n4x + n4c + 4095) >> 12;
    const int cW1 = nActI + 1792;                  // conv done target
    const int nKV = 8 * (B * SKV / 128);
    const int cW2 = cW1 + nKV;
    const int nQ = 4 * (B * SQ / 128);
    const int cW3 = cW2 + nQ;
    const int nAtt = (SQ / 128) * (B * NHEADS);
    const int cW4 = cW3 + nAtt;
    const int nO = (QD / 128) * (B * SQ / 128);
    const int total = cW4 + nO;
    const int kvTgt = 8 * (SKV / 128);             // 64 per batch
    const float qscale = 0.125f * 1.44269504f;

    for (;;) {
        __syncthreads();
        if (tid == 0) shw[0] = atomicAdd(&g_work, 1);
        __syncthreads();
        const int w = shw[0];
        if (w >= total) return;

        if (w < nActI) {
            // ---- activation convert item ----
            int base = (w << 12) + tid;
#pragma unroll
            for (int i = 0; i < 16; i++) {
                int idx = base + (i << 8);
                const float* src;
                __half* dst;
                int k;
                if (idx < n4x) { src = X; dst = xh; k = idx; }
                else if (idx < n4x + n4c) { src = Ctx; dst = ch; k = idx - n4x; }
                else continue;
                float4 v = ((const float4*)src)[k];
                __half hv[4];
                hv[0] = __float2half(v.x); hv[1] = __float2half(v.y);
                hv[2] = __float2half(v.z); hv[3] = __float2half(v.w);
                ((uint2*)dst)[k] = *(uint2*)hv;
            }
            __syncthreads();
            if (tid == 0) red_rel(&g_conv, 1);
            continue;
        }
        if (w < cW1) {
            // ---- weight transpose item ----
            int bid = w - nActI;
            const float* W;
            __half* Wt;
            int K, N, nx;
            if (bid < 512)       { W = Wq; Wt = wqh;  K = QD;   N = INNER; nx = 16; }
            else if (bid < 896)  { bid -= 512;  W = Wk; Wt = wkvh; K = CD; N = INNER; nx = 16; }
            else if (bid < 1280) { bid -= 896;  W = Wv; Wt = wkvh + (size_t)INNER * CD; K = CD; N = INNER; nx = 16; }
            else                 { bid -= 1280; W = Wo; Wt = woh;  K = INNER; N = QD;  nx = 32; }
            const int n0 = (bid % nx) << 5, k0 = (bid / nx) << 5;
            float* t = (float*)smem;                   // [32][33]
            const int tx = tid & 31, ty = tid >> 5;
#pragma unroll
            for (int i = 0; i < 4; i++)
                t[(ty + 8 * i) * 33 + tx] = W[(size_t)(k0 + ty + 8 * i) * N + n0 + tx];
            __syncthreads();
#pragma unroll
            for (int i = 0; i < 4; i++) {
                const int n = n0 + ty + 8 * i;
                const int k = k0 + tx;
                Wt[(size_t)n * K + k] = __float2half(t[tx * 33 + ty + 8 * i]);
            }
            __syncthreads();
            if (tid == 0) red_rel(&g_conv, 1);
            continue;
        }
        if (w >= cW3 && w < cW4) {
            // ---- attention item, order (b, qx, h) ----
            const int a = w - cW3;
            const int b = a >> 8;                      // 256 items per batch
            const int r = a & 255;
            const int qx = r >> 3;
            const int h = r & 7;
            const int rb = b * 32 + qx;
            wait_ge(&g_kv[b], kvTgt);
            wait_ge(&g_qflag[rb * 4 + (h >> 1)], 1);
            attn_core(qs, ks, vs, ah, b, h, qx << 7, smem);
            __syncthreads();
            if (tid == 0) red_rel(&g_attn[rb], 1);
            continue;
        }

        // ---- GEMM tile (KV | Q | O), single gemm_core call site ----
        const __half* A;
        const __half* Bm;
        float* C = nullptr;
        const float* bias = nullptr;
        __half* oS = nullptr;
        __half* oS2 = nullptr;
        float scale = 1.0f;
        int N, K, bx, by;
        int relWhat, relIdx = 0;
        if (w < cW2) {                                  // KV projection
            const int j = w - cW1;
            wait_ge(&g_conv, cW1);
            A = ch; Bm = wkvh; oS = ks; oS2 = vs;
            N = 2 * INNER; K = CD; bx = j & 7; by = j >> 3;
            relWhat = 0; relIdx = (j >> 3) >> 3;
        } else if (w < cW3) {                           // Q projection
            const int i = w - cW2;
            wait_ge(&g_conv, cW1);
            A = xh; Bm = wqh; oS = qs;
            N = INNER; K = QD; scale = qscale; bx = i & 3; by = i >> 2;
            relWhat = 1; relIdx = i;
        } else {                                        // O projection
            const int o = w - cW4;
            by = o >> 3; bx = o & 7;
            wait_ge(&g_attn[by], 8);
            A = ah; Bm = woh; C = out; bias = bo;
            N = QD; K = INNER;
            relWhat = 2;
        }
        gemm_core(A, Bm, C, bias, oS, oS2, scale, N, K, bx, by, smem);
        __syncthreads();
        if (tid == 0) {
            if (relWhat == 0) red_rel(&g_kv[relIdx], 1);
            else if (relWhat == 1) red_rel(&g_qflag[relIdx], 1);
        }
    }
}

// ---------------------------------------------------------------------------
extern "C" void kernel_launch(void* const* d_in, const int* in_sizes, int n_in,
                              void* d_out, int out_size)
{
    const float* x   = (const float*)d_in[0];
    const float* ctx = (const float*)d_in[1];
    const float* Wq  = (const float*)d_in[2];
    const float* Wk  = (const float*)d_in[3];
    const float* Wv  = (const float*)d_in[4];
    const float* Wo  = (const float*)d_in[5];
    const float* bo  = (const float*)d_in[6];
    float* out = (float*)d_out;

    const int B = in_sizes[0] / (SQ * QD);

    cudaFuncSetAttribute(mega, cudaFuncAttributeMaxDynamicSharedMemorySize, TOTAL_SMEM);

    int sms = 148;
    cudaDeviceGetAttribute(&sms, cudaDevAttrMultiProcessorCount, 0);

    reset_counters<<<1, 256>>>();
    mega<<<2 * sms, 256, TOTAL_SMEM>>>(x, ctx, Wq, Wk, Wv, Wo, bo, out, B);
}

// round 14
// speedup vs baseline: 1.1494x; 1.1406x over previous
#include <cuda_runtime.h>
#include <cuda_fp16.h>
#include <cstdint>

#define SQ     4096
#define SKV    1024
#define QD     1024
#define CD     768
#define NHEADS 8
#define DHEAD  64
#define INNER  512
#define BMAX   4

// ---------------- scratch ----------------------------------------------------
__device__ __half g_qs[(size_t)BMAX * SQ * INNER];
__device__ __half g_ks[(size_t)BMAX * SKV * INNER];
__device__ __half g_vs[(size_t)BMAX * SKV * INNER];
__device__ __half g_xh[(size_t)BMAX * SQ * QD];
__device__ __half g_ch[(size_t)BMAX * SKV * CD];
__device__ __half g_ah[(size_t)BMAX * SQ * INNER];
__device__ __half g_wqh[(size_t)INNER * QD];
__device__ __half g_wkvh[(size_t)2 * INNER * CD];
__device__ __half g_woh[(size_t)QD * INNER];

#define NRB (BMAX * SQ / 128)
__device__ int g_attn[NRB];

// ---------------- helpers ----------------------------------------------------
__device__ __forceinline__ uint32_t smem_u32(const void* p) {
    uint32_t a;
    asm("{ .reg .u64 t; cvta.to.shared.u64 t, %1; cvt.u32.u64 %0, t; }" : "=r"(a) : "l"(p));
    return a;
}
__device__ __forceinline__ void cp16(uint32_t dst, const void* src) {
    asm volatile("cp.async.cg.shared.global [%0], [%1], 16;" :: "r"(dst), "l"(src) : "memory");
}
__device__ __forceinline__ void cp_commit() {
    asm volatile("cp.async.commit_group;" ::: "memory");
}
template<int N> __device__ __forceinline__ void cp_wait() {
    asm volatile("cp.async.wait_group %0;" :: "n"(N) : "memory");
}
__device__ __forceinline__ void ldm4(uint32_t* r, uint32_t a) {
    asm volatile("ldmatrix.sync.aligned.m8n8.x4.shared.b16 {%0,%1,%2,%3}, [%4];"
                 : "=r"(r[0]), "=r"(r[1]), "=r"(r[2]), "=r"(r[3]) : "r"(a));
}
__device__ __forceinline__ void ldm4t(uint32_t* r, uint32_t a) {
    asm volatile("ldmatrix.sync.aligned.m8n8.x4.trans.shared.b16 {%0,%1,%2,%3}, [%4];"
                 : "=r"(r[0]), "=r"(r[1]), "=r"(r[2]), "=r"(r[3]) : "r"(a));
}
__device__ __forceinline__ void mma16816(float* c, const uint32_t* a, uint32_t b0, uint32_t b1) {
    asm volatile(
        "mma.sync.aligned.m16n8k16.row.col.f32.f16.f16.f32 "
        "{%0,%1,%2,%3}, {%4,%5,%6,%7}, {%8,%9}, {%0,%1,%2,%3};"
        : "+f"(c[0]), "+f"(c[1]), "+f"(c[2]), "+f"(c[3])
        : "r"(a[0]), "r"(a[1]), "r"(a[2]), "r"(a[3]), "r"(b0), "r"(b1));
}
__device__ __forceinline__ uint32_t pk2h(float lo, float hi) {
    __half2 h = __floats2half2_rn(lo, hi);
    return *reinterpret_cast<uint32_t*>(&h);
}
__device__ __forceinline__ uint32_t ex2h2(uint32_t x) {
    uint32_t r;
    asm("ex2.approx.f16x2 %0, %1;" : "=r"(r) : "r"(x));
    return r;
}
__device__ __forceinline__ uint32_t swz128(uint32_t off) { return off ^ ((off >> 3) & 0x70); }

__device__ __forceinline__ int ldacq(const int* p) {
    int v;
    asm volatile("ld.acquire.gpu.global.b32 %0, [%1];" : "=r"(v) : "l"(p) : "memory");
    return v;
}
__device__ __forceinline__ void red_rel(int* p, int v) {
    asm volatile("red.release.gpu.global.add.s32 [%0], %1;" :: "l"(p), "r"(v) : "memory");
}
__device__ __forceinline__ void wait_ge(const int* p, int tgt) {
    if (threadIdx.x == 0) {
        while (ldacq(p) < tgt) __nanosleep(64);
    }
    __syncthreads();
}

#define ONESH2 0x3C003C00u

// ---------------------------------------------------------------------------
// GEMM core (bit-identical math to R11).
// ---------------------------------------------------------------------------
#define STAGES 3
#define STG_BYTES 32768
#define GEMM_SMEM (STAGES * STG_BYTES)      // 98304

__device__ __forceinline__ void gemm_core(
    const __half* __restrict__ A, const __half* __restrict__ Bm,
    float* __restrict__ C, const float* __restrict__ bias,
    __half* __restrict__ outS, __half* __restrict__ outS2,
    float scale, int N, int Kreal, int bx, int by, char* smem)
{
    const uint32_t sb = smem_u32(smem);
    const int tid = threadIdx.x;
    const int lane = tid & 31;
    const int wid = tid >> 5;
    const int m0 = by << 7;
    const int n0 = bx << 7;
    const int nK = Kreal >> 6;
    const int wm = (wid >> 1) << 5;
    const int wn = (wid & 1) << 6;

    const __half* Ag = A + (size_t)m0 * Kreal;
    const __half* Bg = Bm + (size_t)n0 * Kreal;

    auto load_stage = [&](int kc) {
        const int st = kc % STAGES;
        const uint32_t sa = sb + st * STG_BYTES;
        const uint32_t sbs = sa + 16384;
        const int kb = kc << 6;
#pragma unroll
        for (int i = 0; i < 4; i++) {
            int cid = tid + (i << 8);
            int r = cid >> 3, c8 = cid & 7;
            uint32_t d = swz128((r << 7) + (c8 << 4));
            cp16(sa + d, Ag + (size_t)r * Kreal + kb + (c8 << 3));
            cp16(sbs + d, Bg + (size_t)r * Kreal + kb + (c8 << 3));
        }
        cp_commit();
    };

    float acc[2][8][4];
#pragma unroll
    for (int mi = 0; mi < 2; mi++)
#pragma unroll
        for (int ni = 0; ni < 8; ni++)
#pragma unroll
            for (int j = 0; j < 4; j++) acc[mi][ni][j] = 0.f;

    load_stage(0);
    load_stage(1);

    const uint32_t a_row = wm + (lane & 15);
    const uint32_t a_colb = (lane >> 4) << 4;
    const int q = lane >> 3;
    const uint32_t b_row = wn + ((q >> 1) << 3) + (lane & 7);
    const uint32_t b_colb = (q & 1) << 4;

    for (int kc = 0; kc < nK; kc++) {
        if (kc + 1 < nK) cp_wait<1>(); else cp_wait<0>();
        __syncthreads();
        if (kc + 2 < nK) load_stage(kc + 2);

        const uint32_t sa = sb + (kc % STAGES) * STG_BYTES;
        const uint32_t sbs = sa + 16384;

#pragma unroll
        for (int k16 = 0; k16 < 4; k16++) {
            uint32_t af[2][4];
#pragma unroll
            for (int mi = 0; mi < 2; mi++)
                ldm4(af[mi], sa + swz128(((a_row + mi * 16) << 7) + k16 * 32 + a_colb));
#pragma unroll
            for (int nj = 0; nj < 4; nj++) {
                uint32_t bf[4];
                ldm4(bf, sbs + swz128(((b_row + nj * 16) << 7) + k16 * 32 + b_colb));
#pragma unroll
                for (int mi = 0; mi < 2; mi++) {
                    mma16816(acc[mi][2 * nj],     af[mi], bf[0], bf[1]);
                    mma16816(acc[mi][2 * nj + 1], af[mi], bf[2], bf[3]);
                }
            }
        }
    }

    const int g = lane >> 2, t = lane & 3;
    if (outS2) {
        const int half_ = N >> 1;
#pragma unroll
        for (int mi = 0; mi < 2; mi++) {
#pragma unroll
            for (int ni = 0; ni < 8; ni++) {
                const int col = n0 + wn + ni * 8 + 2 * t;
                __half* base = outS;
                int c2 = col;
                if (col >= half_) { base = outS2; c2 = col - half_; }
#pragma unroll
                for (int rr = 0; rr < 2; rr++) {
                    const int row = m0 + wm + mi * 16 + g + rr * 8;
                    *(uint32_t*)&base[(size_t)row * half_ + c2] =
                        pk2h(acc[mi][ni][2 * rr], acc[mi][ni][2 * rr + 1]);
                }
            }
        }
    } else if (outS) {
#pragma unroll
        for (int mi = 0; mi < 2; mi++) {
#pragma unroll
            for (int ni = 0; ni < 8; ni++) {
                const int col = n0 + wn + ni * 8 + 2 * t;
#pragma unroll
                for (int rr = 0; rr < 2; rr++) {
                    const int row = m0 + wm + mi * 16 + g + rr * 8;
                    *(uint32_t*)&outS[(size_t)row * N + col] =
                        pk2h(acc[mi][ni][2 * rr] * scale, acc[mi][ni][2 * rr + 1] * scale);
                }
            }
        }
    } else {
#pragma unroll
        for (int mi = 0; mi < 2; mi++) {
#pragma unroll
            for (int ni = 0; ni < 8; ni++) {
                const int row = m0 + wm + mi * 16 + g;
                const int col = n0 + wn + ni * 8 + 2 * t;
                float b0 = bias[col], b1 = bias[col + 1];
                float2 v0 = make_float2(acc[mi][ni][0] + b0, acc[mi][ni][1] + b1);
                float2 v1 = make_float2(acc[mi][ni][2] + b0, acc[mi][ni][3] + b1);
                *(float2*)&C[(size_t)row * N + col] = v0;
                *(float2*)&C[(size_t)(row + 8) * N + col] = v1;
            }
        }
    }
}

// ---------------------------------------------------------------------------
// Attention core (bit-identical math to R11).
// ---------------------------------------------------------------------------
__device__ __forceinline__ void attn_core(
    const __half* __restrict__ Qs, const __half* __restrict__ Ks,
    const __half* __restrict__ Vs, __half* __restrict__ AH,
    int b, int h, int q0, char* smem)
{
    const uint32_t Qb = smem_u32(smem);
    const uint32_t KVb = Qb + 16384;
    const int tid = threadIdx.x;
    const int lane = tid & 31;
    const int wid = tid >> 5;

    const __half* Qg = Qs + ((size_t)(b * SQ + q0)) * INNER + h * 64;
    const __half* Kg = Ks + ((size_t)(b * SKV)) * INNER + h * 64;
    const __half* Vg = Vs + ((size_t)(b * SKV)) * INNER + h * 64;

#pragma unroll
    for (int i = 0; i < 4; i++) {
        int cid = (i << 8) + tid;
        int r = cid >> 3, w = cid & 7;
        uint32_t dst = Qb + (r << 7) + ((w << 4) ^ ((r & 7) << 4));
        cp16(dst, Qg + (size_t)r * INNER + w * 8);
    }
    cp_commit();

    auto load_kv = [&](int c) {
        const uint32_t st = KVb + (c & 1) * 16384;
#pragma unroll
        for (int i = 0; i < 4; i++) {
            int cid = (i << 8) + tid;
            int isV = cid >> 9;
            int l9 = cid & 511;
            int r = l9 >> 3, w = l9 & 7;
            const __half* src = (isV ? Vg : Kg) + (size_t)(c * 64 + r) * INNER + w * 8;
            uint32_t dst = st + isV * 8192 + (r << 7) + ((w << 4) ^ ((r & 7) << 4));
            cp16(dst, src);
        }
        cp_commit();
    };
    load_kv(0);
    load_kv(1);

    const int wm = wid << 4;
    const uint32_t a_row = wm + (lane & 15);
    const uint32_t a_csel = (lane >> 4) << 4;
    const int q2 = lane >> 3;
    const uint32_t b_roff = ((q2 >> 1) << 3) + (lane & 7);
    const uint32_t b_csel = (q2 & 1) << 4;
    const uint32_t v_roff = (((lane >> 3) & 1) << 3) + (lane & 7);
    const uint32_t v_csel = (lane >> 4) << 4;

    float o[8][4];
#pragma unroll
    for (int ni = 0; ni < 8; ni++)
#pragma unroll
        for (int j = 0; j < 4; j++) o[ni][j] = 0.f;
    float lacc[4] = {0.f, 0.f, 0.f, 0.f};

    for (int kc = 0; kc < SKV / 64; kc++) {
        if (kc + 1 < SKV / 64) cp_wait<1>(); else cp_wait<0>();
        __syncthreads();
        const uint32_t Kst = KVb + (kc & 1) * 16384;
        const uint32_t Vst = Kst + 8192;

        float s[8][4];
#pragma unroll
        for (int ni = 0; ni < 8; ni++)
#pragma unroll
            for (int j = 0; j < 4; j++) s[ni][j] = 0.f;

#pragma unroll
        for (int k16 = 0; k16 < 4; k16++) {
            uint32_t af[4];
            ldm4(af, Qb + swz128((a_row << 7) + k16 * 32 + a_csel));
#pragma unroll
            for (int nj = 0; nj < 4; nj++) {
                const uint32_t br = nj * 16 + b_roff;
                uint32_t bf[4];
                ldm4(bf, Kst + swz128((br << 7) + k16 * 32 + b_csel));
                mma16816(s[2 * nj],     af, bf[0], bf[1]);
                mma16816(s[2 * nj + 1], af, bf[2], bf[3]);
            }
        }

        uint32_t pf[4][4];
#pragma unroll
        for (int nj = 0; nj < 4; nj++) {
            pf[nj][0] = ex2h2(pk2h(s[2 * nj][0],     s[2 * nj][1]));
            pf[nj][1] = ex2h2(pk2h(s[2 * nj][2],     s[2 * nj][3]));
            pf[nj][2] = ex2h2(pk2h(s[2 * nj + 1][0], s[2 * nj + 1][1]));
            pf[nj][3] = ex2h2(pk2h(s[2 * nj + 1][2], s[2 * nj + 1][3]));
            mma16816(lacc, pf[nj], ONESH2, ONESH2);
        }

#pragma unroll
        for (int j = 0; j < 4; j++) {
            const uint32_t vr = j * 16 + v_roff;
#pragma unroll
            for (int u = 0; u < 4; u++) {
                uint32_t vf[4];
                ldm4t(vf, Vst + swz128((vr << 7) + u * 32 + v_csel));
                mma16816(o[2 * u],     pf[j], vf[0], vf[1]);
                mma16816(o[2 * u + 1], pf[j], vf[2], vf[3]);
            }
        }

        __syncthreads();
        if (kc + 2 < SKV / 64) load_kv(kc + 2);
    }

    const float inv0 = 1.f / lacc[0], inv1 = 1.f / lacc[2];

    const int r0 = q0 + wm + (lane >> 2);
    __half* base0 = AH + (size_t)(b * SQ + r0) * INNER + h * 64;
    __half* base1 = base0 + (size_t)8 * INNER;
#pragma unroll
    for (int ni = 0; ni < 8; ni++) {
        const int dd = ni * 8 + 2 * (lane & 3);
        *(uint32_t*)(base0 + dd) = pk2h(o[ni][0] * inv0, o[ni][1] * inv0);
        *(uint32_t*)(base1 + dd) = pk2h(o[ni][2] * inv1, o[ni][3] * inv1);
    }
}

// ---------------------------------------------------------------------------
// Launch 1: all conversions (identical to R11).
// ---------------------------------------------------------------------------
__global__ void convert_all(const float* __restrict__ X, __half* __restrict__ Xh,
                            const float* __restrict__ Ctx, __half* __restrict__ Ch,
                            const float* __restrict__ Wq, const float* __restrict__ Wk,
                            const float* __restrict__ Wv, const float* __restrict__ Wo,
                            __half* __restrict__ wqh, __half* __restrict__ wkvh,
                            __half* __restrict__ woh,
                            long n4x, long n4c, long nAct)
{
    const int ltid = threadIdx.y * 32 + threadIdx.x;
    if (blockIdx.x < nAct) {
        long i = (long)blockIdx.x * 256 + ltid;
        const float* src;
        __half* dst;
        long idx;
        if (i < n4x) { src = X; dst = Xh; idx = i; }
        else if (i < n4x + n4c) { src = Ctx; dst = Ch; idx = i - n4x; }
        else return;
        float4 v = ((const float4*)src)[idx];
        __half h[4];
        h[0] = __float2half(v.x); h[1] = __float2half(v.y);
        h[2] = __float2half(v.z); h[3] = __float2half(v.w);
        ((uint2*)dst)[idx] = *(uint2*)h;
        return;
    }
    int bid = (int)(blockIdx.x - nAct);
    const float* W;
    __half* Wt;
    int K, N, nx;
    if (bid < 512)       { W = Wq; Wt = wqh;  K = QD;    N = INNER; nx = 16; }
    else if (bid < 896)  { bid -= 512;  W = Wk; Wt = wkvh; K = CD; N = INNER; nx = 16; }
    else if (bid < 1280) { bid -= 896;  W = Wv; Wt = wkvh + (size_t)INNER * CD; K = CD; N = INNER; nx = 16; }
    else                 { bid -= 1280; W = Wo; Wt = woh;  K = INNER; N = QD;  nx = 32; }
    const int n0 = (bid % nx) << 5, k0 = (bid / nx) << 5;

    __shared__ float t[32][33];
    const int tx = threadIdx.x, ty = threadIdx.y;
#pragma unroll
    for (int i = 0; i < 4; i++)
        t[ty + 8 * i][tx] = W[(size_t)(k0 + ty + 8 * i) * N + n0 + tx];
    __syncthreads();
#pragma unroll
    for (int i = 0; i < 4; i++) {
        const int n = n0 + ty + 8 * i;
        const int k = k0 + tx;
        Wt[(size_t)n * K + k] = __float2half(t[tx][ty + 8 * i]);
    }
}

// ---------------------------------------------------------------------------
// Launch 2: fused Q + K|V projections (identical to R11) + g_attn reset.
// ---------------------------------------------------------------------------
__global__ __launch_bounds__(256, 2)
void gemm_qkv(const __half* __restrict__ xh, const __half* __restrict__ wqh,
              const __half* __restrict__ ch, const __half* __restrict__ wkvh,
              __half* __restrict__ qs, __half* __restrict__ ks, __half* __restrict__ vs,
              float qscale, int Mq)
{
    extern __shared__ char smem[];
    // reset attention counters for this replay (visible at next kernel boundary)
    if (blockIdx.x == 0 && threadIdx.x < NRB) g_attn[threadIdx.x] = 0;

    const int nq = (INNER / 128) * (Mq >> 7);
    const int i = blockIdx.x;
    if (i < nq) {
        gemm_core(xh, wqh, nullptr, nullptr, qs, nullptr, qscale,
                  INNER, QD, i & 3, i >> 2, smem);
    } else {
        const int j = i - nq;
        gemm_core(ch, wkvh, nullptr, nullptr, ks, vs, 1.0f,
                  2 * INNER, CD, j & 7, j >> 3, smem);
    }
}

// ---------------------------------------------------------------------------
// Launch 3: fused attention + O-projection, static blockIdx split.
// Blocks [0, B*256): attention tiles, rb-major (b, qx, h) — so g_attn[rb]
// reaches 8 in increasing-rb order. Blocks [B*256, B*512): O tiles, rb-major;
// each waits on g_attn[by] >= 8 (near-zero spin by construction).
// ---------------------------------------------------------------------------
__global__ __launch_bounds__(256, 2)
void attn_o(const __half* __restrict__ qs, const __half* __restrict__ ks,
            const __half* __restrict__ vs, __half* __restrict__ ah,
            const __half* __restrict__ woh, float* __restrict__ out,
            const float* __restrict__ bo, int B)
{
    extern __shared__ char smem[];
    const int w = blockIdx.x;
    const int nAtt = B << 8;

    if (w < nAtt) {
        const int b = w >> 8;
        const int r = w & 255;
        const int qx = r >> 3;
        const int h = r & 7;
        attn_core(qs, ks, vs, ah, b, h, qx << 7, smem);
        __syncthreads();
        if (threadIdx.x == 0) red_rel(&g_attn[b * 32 + qx], 1);
    } else {
        const int o = w - nAtt;
        const int by = o >> 3;
        const int bx = o & 7;
        wait_ge(&g_attn[by], 8);
        gemm_core(ah, woh, out, bo, nullptr, nullptr, 1.0f,
                  QD, INNER, bx, by, smem);
    }
}

// ---------------------------------------------------------------------------
extern "C" void kernel_launch(void* const* d_in, const int* in_sizes, int n_in,
                              void* d_out, int out_size)
{
    const float* x   = (const float*)d_in[0];
    const float* ctx = (const float*)d_in[1];
    const float* Wq  = (const float*)d_in[2];
    const float* Wk  = (const float*)d_in[3];
    const float* Wv  = (const float*)d_in[4];
    const float* Wo  = (const float*)d_in[5];
    const float* bo  = (const float*)d_in[6];
    float* out = (float*)d_out;

    const int B = in_sizes[0] / (SQ * QD);

    __half *qs, *ks, *vs, *xh, *ch, *ah, *wqh, *wkvh, *woh;
    cudaGetSymbolAddress((void**)&qs, g_qs);
    cudaGetSymbolAddress((void**)&ks, g_ks);
    cudaGetSymbolAddress((void**)&vs, g_vs);
    cudaGetSymbolAddress((void**)&xh, g_xh);
    cudaGetSymbolAddress((void**)&ch, g_ch);
    cudaGetSymbolAddress((void**)&ah, g_ah);
    cudaGetSymbolAddress((void**)&wqh, g_wqh);
    cudaGetSymbolAddress((void**)&wkvh, g_wkvh);
    cudaGetSymbolAddress((void**)&woh, g_woh);

    cudaFuncSetAttribute(gemm_qkv, cudaFuncAttributeMaxDynamicSharedMemorySize, GEMM_SMEM);
    cudaFuncSetAttribute(attn_o,   cudaFuncAttributeMaxDynamicSharedMemorySize, GEMM_SMEM);

    // --- launch 1: all conversions ---
    {
        long n4x = (long)B * SQ * QD / 4;
        long n4c = (long)B * SKV * CD / 4;
        long nAct = (n4x + n4c + 255) / 256;
        convert_all<<<(unsigned)(nAct + 1792), dim3(32, 8)>>>(
            x, xh, ctx, ch, Wq, Wk, Wv, Wo, wqh, wkvh, woh, n4x, n4c, nAct);
    }

    // --- launch 2: fused Q + K|V projections (+ counter reset) ---
    const float qscale = 0.125f * 1.44269504f;
    const int nq = (INNER / 128) * (B * SQ / 128);
    const int nkv = (2 * INNER / 128) * (B * SKV / 128);
    gemm_qkv<<<nq + nkv, 256, GEMM_SMEM>>>(xh, wqh, ch, wkvh, qs, ks, vs,
                                           qscale, B * SQ);

    // --- launch 3: fused attention + O-projection ---
    attn_o<<<B * 512, 256, GEMM_SMEM>>>(qs, ks, vs, ah, woh, out, bo, B);
}

// round 15
// speedup vs baseline: 1.1497x; 1.0003x over previous
#include <cuda_runtime.h>
#include <cuda_fp16.h>
#include <cstdint>

#define SQ     4096
#define SKV    1024
#define QD     1024
#define CD     768
#define NHEADS 8
#define DHEAD  64
#define INNER  512
#define BMAX   4

// ---------------- scratch ----------------------------------------------------
__device__ __half g_qs[(size_t)BMAX * SQ * INNER];
__device__ __half g_ks[(size_t)BMAX * SKV * INNER];
__device__ __half g_vs[(size_t)BMAX * SKV * INNER];
__device__ __half g_xh[(size_t)BMAX * SQ * QD];
__device__ __half g_ch[(size_t)BMAX * SKV * CD];
__device__ __half g_ah[(size_t)BMAX * SQ * INNER];
__device__ __half g_wqh[(size_t)INNER * QD];
__device__ __half g_wkvh[(size_t)2 * INNER * CD];
__device__ __half g_woh[(size_t)QD * INNER];

#define NRB (BMAX * SQ / 128)     // 128
#define NCB (BMAX * SKV / 128)    // 32
__device__ int g_attn[NRB];
__device__ int g_xc[NRB];
__device__ int g_cc[NCB];
__device__ int g_wq;
__device__ int g_wkv;

// ---------------- helpers ----------------------------------------------------
__device__ __forceinline__ uint32_t smem_u32(const void* p) {
    uint32_t a;
    asm("{ .reg .u64 t; cvta.to.shared.u64 t, %1; cvt.u32.u64 %0, t; }" : "=r"(a) : "l"(p));
    return a;
}
__device__ __forceinline__ void cp16(uint32_t dst, const void* src) {
    asm volatile("cp.async.cg.shared.global [%0], [%1], 16;" :: "r"(dst), "l"(src) : "memory");
}
__device__ __forceinline__ void cp_commit() {
    asm volatile("cp.async.commit_group;" ::: "memory");
}
template<int N> __device__ __forceinline__ void cp_wait() {
    asm volatile("cp.async.wait_group %0;" :: "n"(N) : "memory");
}
__device__ __forceinline__ void ldm4(uint32_t* r, uint32_t a) {
    asm volatile("ldmatrix.sync.aligned.m8n8.x4.shared.b16 {%0,%1,%2,%3}, [%4];"
                 : "=r"(r[0]), "=r"(r[1]), "=r"(r[2]), "=r"(r[3]) : "r"(a));
}
__device__ __forceinline__ void ldm4t(uint32_t* r, uint32_t a) {
    asm volatile("ldmatrix.sync.aligned.m8n8.x4.trans.shared.b16 {%0,%1,%2,%3}, [%4];"
                 : "=r"(r[0]), "=r"(r[1]), "=r"(r[2]), "=r"(r[3]) : "r"(a));
}
__device__ __forceinline__ void mma16816(float* c, const uint32_t* a, uint32_t b0, uint32_t b1) {
    asm volatile(
        "mma.sync.aligned.m16n8k16.row.col.f32.f16.f16.f32 "
        "{%0,%1,%2,%3}, {%4,%5,%6,%7}, {%8,%9}, {%0,%1,%2,%3};"
        : "+f"(c[0]), "+f"(c[1]), "+f"(c[2]), "+f"(c[3])
        : "r"(a[0]), "r"(a[1]), "r"(a[2]), "r"(a[3]), "r"(b0), "r"(b1));
}
__device__ __forceinline__ uint32_t pk2h(float lo, float hi) {
    __half2 h = __floats2half2_rn(lo, hi);
    return *reinterpret_cast<uint32_t*>(&h);
}
__device__ __forceinline__ uint32_t ex2h2(uint32_t x) {
    uint32_t r;
    asm("ex2.approx.f16x2 %0, %1;" : "=r"(r) : "r"(x));
    return r;
}
__device__ __forceinline__ uint32_t swz128(uint32_t off) { return off ^ ((off >> 3) & 0x70); }

__device__ __forceinline__ int ldacq(const int* p) {
    int v;
    asm volatile("ld.acquire.gpu.global.b32 %0, [%1];" : "=r"(v) : "l"(p) : "memory");
    return v;
}
__device__ __forceinline__ void red_rel(int* p, int v) {
    asm volatile("red.release.gpu.global.add.s32 [%0], %1;" :: "l"(p), "r"(v) : "memory");
}
__device__ __forceinline__ void wait_ge(const int* p, int tgt) {
    if (threadIdx.x == 0) {
        while (ldacq(p) < tgt) __nanosleep(64);
    }
    __syncthreads();
}

#define ONESH2 0x3C003C00u

// ---------------------------------------------------------------------------
// GEMM core (bit-identical math since R11).
// ---------------------------------------------------------------------------
#define STAGES 3
#define STG_BYTES 32768
#define GEMM_SMEM (STAGES * STG_BYTES)      // 98304

__device__ __forceinline__ void gemm_core(
    const __half* __restrict__ A, const __half* __restrict__ Bm,
    float* __restrict__ C, const float* __restrict__ bias,
    __half* __restrict__ outS, __half* __restrict__ outS2,
    float scale, int N, int Kreal, int bx, int by, char* smem)
{
    const uint32_t sb = smem_u32(smem);
    const int tid = threadIdx.x;
    const int lane = tid & 31;
    const int wid = tid >> 5;
    const int m0 = by << 7;
    const int n0 = bx << 7;
    const int nK = Kreal >> 6;
    const int wm = (wid >> 1) << 5;
    const int wn = (wid & 1) << 6;

    const __half* Ag = A + (size_t)m0 * Kreal;
    const __half* Bg = Bm + (size_t)n0 * Kreal;

    auto load_stage = [&](int kc) {
        const int st = kc % STAGES;
        const uint32_t sa = sb + st * STG_BYTES;
        const uint32_t sbs = sa + 16384;
        const int kb = kc << 6;
#pragma unroll
        for (int i = 0; i < 4; i++) {
            int cid = tid + (i << 8);
            int r = cid >> 3, c8 = cid & 7;
            uint32_t d = swz128((r << 7) + (c8 << 4));
            cp16(sa + d, Ag + (size_t)r * Kreal + kb + (c8 << 3));
            cp16(sbs + d, Bg + (size_t)r * Kreal + kb + (c8 << 3));
        }
        cp_commit();
    };

    float acc[2][8][4];
#pragma unroll
    for (int mi = 0; mi < 2; mi++)
#pragma unroll
        for (int ni = 0; ni < 8; ni++)
#pragma unroll
            for (int j = 0; j < 4; j++) acc[mi][ni][j] = 0.f;

    load_stage(0);
    load_stage(1);

    const uint32_t a_row = wm + (lane & 15);
    const uint32_t a_colb = (lane >> 4) << 4;
    const int q = lane >> 3;
    const uint32_t b_row = wn + ((q >> 1) << 3) + (lane & 7);
    const uint32_t b_colb = (q & 1) << 4;

    for (int kc = 0; kc < nK; kc++) {
        if (kc + 1 < nK) cp_wait<1>(); else cp_wait<0>();
        __syncthreads();
        if (kc + 2 < nK) load_stage(kc + 2);

        const uint32_t sa = sb + (kc % STAGES) * STG_BYTES;
        const uint32_t sbs = sa + 16384;

#pragma unroll
        for (int k16 = 0; k16 < 4; k16++) {
            uint32_t af[2][4];
#pragma unroll
            for (int mi = 0; mi < 2; mi++)
                ldm4(af[mi], sa + swz128(((a_row + mi * 16) << 7) + k16 * 32 + a_colb));
#pragma unroll
            for (int nj = 0; nj < 4; nj++) {
                uint32_t bf[4];
                ldm4(bf, sbs + swz128(((b_row + nj * 16) << 7) + k16 * 32 + b_colb));
#pragma unroll
                for (int mi = 0; mi < 2; mi++) {
                    mma16816(acc[mi][2 * nj],     af[mi], bf[0], bf[1]);
                    mma16816(acc[mi][2 * nj + 1], af[mi], bf[2], bf[3]);
                }
            }
        }
    }

    const int g = lane >> 2, t = lane & 3;
    if (outS2) {
        const int half_ = N >> 1;
#pragma unroll
        for (int mi = 0; mi < 2; mi++) {
#pragma unroll
            for (int ni = 0; ni < 8; ni++) {
                const int col = n0 + wn + ni * 8 + 2 * t;
                __half* base = outS;
                int c2 = col;
                if (col >= half_) { base = outS2; c2 = col - half_; }
#pragma unroll
                for (int rr = 0; rr < 2; rr++) {
                    const int row = m0 + wm + mi * 16 + g + rr * 8;
                    *(uint32_t*)&base[(size_t)row * half_ + c2] =
                        pk2h(acc[mi][ni][2 * rr], acc[mi][ni][2 * rr + 1]);
                }
            }
        }
    } else if (outS) {
#pragma unroll
        for (int mi = 0; mi < 2; mi++) {
#pragma unroll
            for (int ni = 0; ni < 8; ni++) {
                const int col = n0 + wn + ni * 8 + 2 * t;
#pragma unroll
                for (int rr = 0; rr < 2; rr++) {
                    const int row = m0 + wm + mi * 16 + g + rr * 8;
                    *(uint32_t*)&outS[(size_t)row * N + col] =
                        pk2h(acc[mi][ni][2 * rr] * scale, acc[mi][ni][2 * rr + 1] * scale);
                }
            }
        }
    } else {
#pragma unroll
        for (int mi = 0; mi < 2; mi++) {
#pragma unroll
            for (int ni = 0; ni < 8; ni++) {
                const int row = m0 + wm + mi * 16 + g;
                const int col = n0 + wn + ni * 8 + 2 * t;
                float b0 = bias[col], b1 = bias[col + 1];
                float2 v0 = make_float2(acc[mi][ni][0] + b0, acc[mi][ni][1] + b1);
                float2 v1 = make_float2(acc[mi][ni][2] + b0, acc[mi][ni][3] + b1);
                *(float2*)&C[(size_t)row * N + col] = v0;
                *(float2*)&C[(size_t)(row + 8) * N + col] = v1;
            }
        }
    }
}

// ---------------------------------------------------------------------------
// Attention core (bit-identical math since R11).
// ---------------------------------------------------------------------------
__device__ __forceinline__ void attn_core(
    const __half* __restrict__ Qs, const __half* __restrict__ Ks,
    const __half* __restrict__ Vs, __half* __restrict__ AH,
    int b, int h, int q0, char* smem)
{
    const uint32_t Qb = smem_u32(smem);
    const uint32_t KVb = Qb + 16384;
    const int tid = threadIdx.x;
    const int lane = tid & 31;
    const int wid = tid >> 5;

    const __half* Qg = Qs + ((size_t)(b * SQ + q0)) * INNER + h * 64;
    const __half* Kg = Ks + ((size_t)(b * SKV)) * INNER + h * 64;
    const __half* Vg = Vs + ((size_t)(b * SKV)) * INNER + h * 64;

#pragma unroll
    for (int i = 0; i < 4; i++) {
        int cid = (i << 8) + tid;
        int r = cid >> 3, w = cid & 7;
        uint32_t dst = Qb + (r << 7) + ((w << 4) ^ ((r & 7) << 4));
        cp16(dst, Qg + (size_t)r * INNER + w * 8);
    }
    cp_commit();

    auto load_kv = [&](int c) {
        const uint32_t st = KVb + (c & 1) * 16384;
#pragma unroll
        for (int i = 0; i < 4; i++) {
            int cid = (i << 8) + tid;
            int isV = cid >> 9;
            int l9 = cid & 511;
            int r = l9 >> 3, w = l9 & 7;
            const __half* src = (isV ? Vg : Kg) + (size_t)(c * 64 + r) * INNER + w * 8;
            uint32_t dst = st + isV * 8192 + (r << 7) + ((w << 4) ^ ((r & 7) << 4));
            cp16(dst, src);
        }
        cp_commit();
    };
    load_kv(0);
    load_kv(1);

    const int wm = wid << 4;
    const uint32_t a_row = wm + (lane & 15);
    const uint32_t a_csel = (lane >> 4) << 4;
    const int q2 = lane >> 3;
    const uint32_t b_roff = ((q2 >> 1) << 3) + (lane & 7);
    const uint32_t b_csel = (q2 & 1) << 4;
    const uint32_t v_roff = (((lane >> 3) & 1) << 3) + (lane & 7);
    const uint32_t v_csel = (lane >> 4) << 4;

    float o[8][4];
#pragma unroll
    for (int ni = 0; ni < 8; ni++)
#pragma unroll
        for (int j = 0; j < 4; j++) o[ni][j] = 0.f;
    float lacc[4] = {0.f, 0.f, 0.f, 0.f};

    for (int kc = 0; kc < SKV / 64; kc++) {
        if (kc + 1 < SKV / 64) cp_wait<1>(); else cp_wait<0>();
        __syncthreads();
        const uint32_t Kst = KVb + (kc & 1) * 16384;
        const uint32_t Vst = Kst + 8192;

        float s[8][4];
#pragma unroll
        for (int ni = 0; ni < 8; ni++)
#pragma unroll
            for (int j = 0; j < 4; j++) s[ni][j] = 0.f;

#pragma unroll
        for (int k16 = 0; k16 < 4; k16++) {
            uint32_t af[4];
            ldm4(af, Qb + swz128((a_row << 7) + k16 * 32 + a_csel));
#pragma unroll
            for (int nj = 0; nj < 4; nj++) {
                const uint32_t br = nj * 16 + b_roff;
                uint32_t bf[4];
                ldm4(bf, Kst + swz128((br << 7) + k16 * 32 + b_csel));
                mma16816(s[2 * nj],     af, bf[0], bf[1]);
                mma16816(s[2 * nj + 1], af, bf[2], bf[3]);
            }
        }

        uint32_t pf[4][4];
#pragma unroll
        for (int nj = 0; nj < 4; nj++) {
            pf[nj][0] = ex2h2(pk2h(s[2 * nj][0],     s[2 * nj][1]));
            pf[nj][1] = ex2h2(pk2h(s[2 * nj][2],     s[2 * nj][3]));
            pf[nj][2] = ex2h2(pk2h(s[2 * nj + 1][0], s[2 * nj + 1][1]));
            pf[nj][3] = ex2h2(pk2h(s[2 * nj + 1][2], s[2 * nj + 1][3]));
            mma16816(lacc, pf[nj], ONESH2, ONESH2);
        }

#pragma unroll
        for (int j = 0; j < 4; j++) {
            const uint32_t vr = j * 16 + v_roff;
#pragma unroll
            for (int u = 0; u < 4; u++) {
                uint32_t vf[4];
                ldm4t(vf, Vst + swz128((vr << 7) + u * 32 + v_csel));
                mma16816(o[2 * u],     pf[j], vf[0], vf[1]);
                mma16816(o[2 * u + 1], pf[j], vf[2], vf[3]);
            }
        }

        __syncthreads();
        if (kc + 2 < SKV / 64) load_kv(kc + 2);
    }

    const float inv0 = 1.f / lacc[0], inv1 = 1.f / lacc[2];

    const int r0 = q0 + wm + (lane >> 2);
    __half* base0 = AH + (size_t)(b * SQ + r0) * INNER + h * 64;
    __half* base1 = base0 + (size_t)8 * INNER;
#pragma unroll
    for (int ni = 0; ni < 8; ni++) {
        const int dd = ni * 8 + 2 * (lane & 3);
        *(uint32_t*)(base0 + dd) = pk2h(o[ni][0] * inv0, o[ni][1] * inv0);
        *(uint32_t*)(base1 + dd) = pk2h(o[ni][2] * inv1, o[ni][3] * inv1);
    }
}

// ---------------------------------------------------------------------------
// Launch 1: fused converts + QKV projections.
// Items: [x-conv (nX) | ctx-conv (nC) | weight transposes (1792) |
//         Q tiles (nQ) | KV tiles (nKV)].
// Q tiles wait g_wq==512 && g_xc[by]; KV tiles wait g_wkv==768 && g_cc[by].
// Converts occupy strictly lower blockIdx -> short spins, no deadlock.
// Block 0 also resets g_attn for this replay's attn_o.
// ---------------------------------------------------------------------------
__global__ __launch_bounds__(256, 2)
void conv_qkv(const float* __restrict__ X, const float* __restrict__ Ctx,
              const float* __restrict__ Wq, const float* __restrict__ Wk,
              const float* __restrict__ Wv, const float* __restrict__ Wo,
              __half* __restrict__ xh, __half* __restrict__ ch,
              __half* __restrict__ wqh, __half* __restrict__ wkvh,
              __half* __restrict__ woh,
              __half* __restrict__ qs, __half* __restrict__ ks,
              __half* __restrict__ vs, float qscale, int B)
{
    extern __shared__ char smem[];
    const int tid = threadIdx.x;
    const int w = blockIdx.x;
    const int nX = B * SQ / 128;           // 128
    const int nC = B * SKV / 128;          // 32
    const int cW = nX + nC + 1792;
    const int nQ = 4 * (B * SQ / 128);     // 512

    if (w == 0 && tid < NRB) g_attn[tid] = 0;

    if (w < nX) {
        // ---- x convert: rows w*128.., 256 float4 per row ----
        long base = (long)w << 15;          // * 32768
#pragma unroll 8
        for (int i = 0; i < 128; i++) {
            long idx = base + tid + (i << 8);
            float4 v = ((const float4*)X)[idx];
            __half hv[4];
            hv[0] = __float2half(v.x); hv[1] = __float2half(v.y);
            hv[2] = __float2half(v.z); hv[3] = __float2half(v.w);
            ((uint2*)xh)[idx] = *(uint2*)hv;
        }
        __syncthreads();
        if (tid == 0) red_rel(&g_xc[w], 1);
        return;
    }
    if (w < nX + nC) {
        // ---- ctx convert: rows c*128.., 192 float4 per row ----
        const int c = w - nX;
        long base = (long)c * 24576;
#pragma unroll 8
        for (int i = 0; i < 96; i++) {
            long idx = base + tid + (i << 8);
            float4 v = ((const float4*)Ctx)[idx];
            __half hv[4];
            hv[0] = __float2half(v.x); hv[1] = __float2half(v.y);
            hv[2] = __float2half(v.z); hv[3] = __float2half(v.w);
            ((uint2*)ch)[idx] = *(uint2*)hv;
        }
        __syncthreads();
        if (tid == 0) red_rel(&g_cc[c], 1);
        return;
    }
    if (w < cW) {
        // ---- weight transpose item ----
        int bid = w - nX - nC;
        const int cls = (bid < 512) ? 0 : (bid < 1280 ? 1 : 2);
        const float* W;
        __half* Wt;
        int K, N, nx;
        if (bid < 512)       { W = Wq; Wt = wqh;  K = QD;   N = INNER; nx = 16; }
        else if (bid < 896)  { bid -= 512;  W = Wk; Wt = wkvh; K = CD; N = INNER; nx = 16; }
        else if (bid < 1280) { bid -= 896;  W = Wv; Wt = wkvh + (size_t)INNER * CD; K = CD; N = INNER; nx = 16; }
        else                 { bid -= 1280; W = Wo; Wt = woh;  K = INNER; N = QD;  nx = 32; }
        const int n0 = (bid % nx) << 5, k0 = (bid / nx) << 5;
        float* t = (float*)smem;                // [32][33]
        const int tx = tid & 31, ty = tid >> 5;
#pragma unroll
        for (int i = 0; i < 4; i++)
            t[(ty + 8 * i) * 33 + tx] = W[(size_t)(k0 + ty + 8 * i) * N + n0 + tx];
        __syncthreads();
#pragma unroll
        for (int i = 0; i < 4; i++) {
            const int n = n0 + ty + 8 * i;
            const int k = k0 + tx;
            Wt[(size_t)n * K + k] = __float2half(t[tx * 33 + ty + 8 * i]);
        }
        __syncthreads();
        if (tid == 0) {
            if (cls == 0) red_rel(&g_wq, 1);
            else if (cls == 1) red_rel(&g_wkv, 1);
        }
        return;
    }

    const int g = w - cW;
    if (g < nQ) {
        const int by = g >> 2, bx = g & 3;
        wait_ge(&g_wq, 512);
        wait_ge(&g_xc[by], 1);
        gemm_core(xh, wqh, nullptr, nullptr, qs, nullptr, qscale,
                  INNER, QD, bx, by, smem);
    } else {
        const int j = g - nQ;
        const int by = j >> 3, bx = j & 7;
        wait_ge(&g_wkv, 768);
        wait_ge(&g_cc[by], 1);
        gemm_core(ch, wkvh, nullptr, nullptr, ks, vs, 1.0f,
                  2 * INNER, CD, bx, by, smem);
    }
}

// ---------------------------------------------------------------------------
// Launch 2: fused attention + O-projection (identical to R14).
// Block 0 also resets the front-end counters for the NEXT replay.
// ---------------------------------------------------------------------------
__global__ __launch_bounds__(256, 2)
void attn_o(const __half* __restrict__ qs, const __half* __restrict__ ks,
            const __half* __restrict__ vs, __half* __restrict__ ah,
            const __half* __restrict__ woh, float* __restrict__ out,
            const float* __restrict__ bo, int B)
{
    extern __shared__ char smem[];
    const int w = blockIdx.x;
    const int nAtt = B << 8;

    if (w == 0) {
        // reset front-end counters for the next graph replay
        if (threadIdx.x < NRB) g_xc[threadIdx.x] = 0;
        if (threadIdx.x < NCB) g_cc[threadIdx.x] = 0;
        if (threadIdx.x == 0) { g_wq = 0; g_wkv = 0; }
    }

    if (w < nAtt) {
        const int b = w >> 8;
        const int r = w & 255;
        const int qx = r >> 3;
        const int h = r & 7;
        attn_core(qs, ks, vs, ah, b, h, qx << 7, smem);
        __syncthreads();
        if (threadIdx.x == 0) red_rel(&g_attn[b * 32 + qx], 1);
    } else {
        const int o = w - nAtt;
        const int by = o >> 3;
        const int bx = o & 7;
        wait_ge(&g_attn[by], 8);
        gemm_core(ah, woh, out, bo, nullptr, nullptr, 1.0f,
                  QD, INNER, bx, by, smem);
    }
}

// ---------------------------------------------------------------------------
extern "C" void kernel_launch(void* const* d_in, const int* in_sizes, int n_in,
                              void* d_out, int out_size)
{
    const float* x   = (const float*)d_in[0];
    const float* ctx = (const float*)d_in[1];
    const float* Wq  = (const float*)d_in[2];
    const float* Wk  = (const float*)d_in[3];
    const float* Wv  = (const float*)d_in[4];
    const float* Wo  = (const float*)d_in[5];
    const float* bo  = (const float*)d_in[6];
    float* out = (float*)d_out;

    const int B = in_sizes[0] / (SQ * QD);

    __half *qs, *ks, *vs, *xh, *ch, *ah, *wqh, *wkvh, *woh;
    cudaGetSymbolAddress((void**)&qs, g_qs);
    cudaGetSymbolAddress((void**)&ks, g_ks);
    cudaGetSymbolAddress((void**)&vs, g_vs);
    cudaGetSymbolAddress((void**)&xh, g_xh);
    cudaGetSymbolAddress((void**)&ch, g_ch);
    cudaGetSymbolAddress((void**)&ah, g_ah);
    cudaGetSymbolAddress((void**)&wqh, g_wqh);
    cudaGetSymbolAddress((void**)&wkvh, g_wkvh);
    cudaGetSymbolAddress((void**)&woh, g_woh);

    cudaFuncSetAttribute(conv_qkv, cudaFuncAttributeMaxDynamicSharedMemorySize, GEMM_SMEM);
    cudaFuncSetAttribute(attn_o,   cudaFuncAttributeMaxDynamicSharedMemorySize, GEMM_SMEM);

    const float qscale = 0.125f * 1.44269504f;
    const int nX = B * SQ / 128;
    const int nC = B * SKV / 128;
    const int nQ = 4 * (B * SQ / 128);
    const int nKV = 8 * (B * SKV / 128);
    const int gridA = nX + nC + 1792 + nQ + nKV;

    // --- launch 1: converts + QKV projections ---
    conv_qkv<<<gridA, 256, GEMM_SMEM>>>(x, ctx, Wq, Wk, Wv, Wo,
                                        xh, ch, wqh, wkvh, woh,
                                        qs, ks, vs, qscale, B);

    // --- launch 2: attention + O-projection ---
    attn_o<<<B * 512, 256, GEMM_SMEM>>>(qs, ks, vs, ah, woh, out, bo, B);
}

// round 16
// speedup vs baseline: 1.1912x; 1.0361x over previous
#include <cuda_runtime.h>
#include <cuda_fp16.h>
#include <cstdint>

#define SQ     4096
#define SKV    1024
#define QD     1024
#define CD     768
#define NHEADS 8
#define DHEAD  64
#define INNER  512
#define BMAX   4

// ---------------- scratch ----------------------------------------------------
__device__ __half g_qs[(size_t)BMAX * SQ * INNER];
__device__ __half g_ks[(size_t)BMAX * SKV * INNER];
__device__ __half g_vs[(size_t)BMAX * SKV * INNER];
__device__ __half g_xh[(size_t)BMAX * SQ * QD];
__device__ __half g_ch[(size_t)BMAX * SKV * CD];
__device__ __half g_ah[(size_t)BMAX * SQ * INNER];
__device__ __half g_wqh[(size_t)INNER * QD];
__device__ __half g_wkvh[(size_t)2 * INNER * CD];
__device__ __half g_woh[(size_t)QD * INNER];

#define NRB (BMAX * SQ / 128)     // 128
#define NCB (BMAX * SKV / 128)    // 32
__device__ int g_attn[NRB];
__device__ int g_xc[NRB];
__device__ int g_cc[NCB];
__device__ int g_wq;
__device__ int g_wkv;
__device__ int g_kv[BMAX];
__device__ int g_qflag[NRB * 4];

// ---------------- helpers ----------------------------------------------------
__device__ __forceinline__ uint32_t smem_u32(const void* p) {
    uint32_t a;
    asm("{ .reg .u64 t; cvta.to.shared.u64 t, %1; cvt.u32.u64 %0, t; }" : "=r"(a) : "l"(p));
    return a;
}
__device__ __forceinline__ void cp16(uint32_t dst, const void* src) {
    asm volatile("cp.async.cg.shared.global [%0], [%1], 16;" :: "r"(dst), "l"(src) : "memory");
}
__device__ __forceinline__ void cp_commit() {
    asm volatile("cp.async.commit_group;" ::: "memory");
}
template<int N> __device__ __forceinline__ void cp_wait() {
    asm volatile("cp.async.wait_group %0;" :: "n"(N) : "memory");
}
__device__ __forceinline__ void ldm4(uint32_t* r, uint32_t a) {
    asm volatile("ldmatrix.sync.aligned.m8n8.x4.shared.b16 {%0,%1,%2,%3}, [%4];"
                 : "=r"(r[0]), "=r"(r[1]), "=r"(r[2]), "=r"(r[3]) : "r"(a));
}
__device__ __forceinline__ void ldm4t(uint32_t* r, uint32_t a) {
    asm volatile("ldmatrix.sync.aligned.m8n8.x4.trans.shared.b16 {%0,%1,%2,%3}, [%4];"
                 : "=r"(r[0]), "=r"(r[1]), "=r"(r[2]), "=r"(r[3]) : "r"(a));
}
__device__ __forceinline__ void mma16816(float* c, const uint32_t* a, uint32_t b0, uint32_t b1) {
    asm volatile(
        "mma.sync.aligned.m16n8k16.row.col.f32.f16.f16.f32 "
        "{%0,%1,%2,%3}, {%4,%5,%6,%7}, {%8,%9}, {%0,%1,%2,%3};"
        : "+f"(c[0]), "+f"(c[1]), "+f"(c[2]), "+f"(c[3])
        : "r"(a[0]), "r"(a[1]), "r"(a[2]), "r"(a[3]), "r"(b0), "r"(b1));
}
__device__ __forceinline__ uint32_t pk2h(float lo, float hi) {
    __half2 h = __floats2half2_rn(lo, hi);
    return *reinterpret_cast<uint32_t*>(&h);
}
__device__ __forceinline__ uint32_t ex2h2(uint32_t x) {
    uint32_t r;
    asm("ex2.approx.f16x2 %0, %1;" : "=r"(r) : "r"(x));
    return r;
}
__device__ __forceinline__ uint32_t swz128(uint32_t off) { return off ^ ((off >> 3) & 0x70); }

__device__ __forceinline__ int ldacq(const int* p) {
    int v;
    asm volatile("ld.acquire.gpu.global.b32 %0, [%1];" : "=r"(v) : "l"(p) : "memory");
    return v;
}
__device__ __forceinline__ void red_rel(int* p, int v) {
    asm volatile("red.release.gpu.global.add.s32 [%0], %1;" :: "l"(p), "r"(v) : "memory");
}
__device__ __forceinline__ void wait_ge(const int* p, int tgt) {
    if (threadIdx.x == 0) {
        while (ldacq(p) < tgt) __nanosleep(64);
    }
    __syncthreads();
}

#define ONESH2 0x3C003C00u

// ---------------------------------------------------------------------------
// GEMM core (bit-identical math since R11).
// ---------------------------------------------------------------------------
#define STAGES 3
#define STG_BYTES 32768
#define GEMM_SMEM (STAGES * STG_BYTES)      // 98304

__device__ __forceinline__ void gemm_core(
    const __half* __restrict__ A, const __half* __restrict__ Bm,
    float* __restrict__ C, const float* __restrict__ bias,
    __half* __restrict__ outS, __half* __restrict__ outS2,
    float scale, int N, int Kreal, int bx, int by, char* smem)
{
    const uint32_t sb = smem_u32(smem);
    const int tid = threadIdx.x;
    const int lane = tid & 31;
    const int wid = tid >> 5;
    const int m0 = by << 7;
    const int n0 = bx << 7;
    const int nK = Kreal >> 6;
    const int wm = (wid >> 1) << 5;
    const int wn = (wid & 1) << 6;

    const __half* Ag = A + (size_t)m0 * Kreal;
    const __half* Bg = Bm + (size_t)n0 * Kreal;

    auto load_stage = [&](int kc) {
        const int st = kc % STAGES;
        const uint32_t sa = sb + st * STG_BYTES;
        const uint32_t sbs = sa + 16384;
        const int kb = kc << 6;
#pragma unroll
        for (int i = 0; i < 4; i++) {
            int cid = tid + (i << 8);
            int r = cid >> 3, c8 = cid & 7;
            uint32_t d = swz128((r << 7) + (c8 << 4));
            cp16(sa + d, Ag + (size_t)r * Kreal + kb + (c8 << 3));
            cp16(sbs + d, Bg + (size_t)r * Kreal + kb + (c8 << 3));
        }
        cp_commit();
    };

    float acc[2][8][4];
#pragma unroll
    for (int mi = 0; mi < 2; mi++)
#pragma unroll
        for (int ni = 0; ni < 8; ni++)
#pragma unroll
            for (int j = 0; j < 4; j++) acc[mi][ni][j] = 0.f;

    load_stage(0);
    load_stage(1);

    const uint32_t a_row = wm + (lane & 15);
    const uint32_t a_colb = (lane >> 4) << 4;
    const int q = lane >> 3;
    const uint32_t b_row = wn + ((q >> 1) << 3) + (lane & 7);
    const uint32_t b_colb = (q & 1) << 4;

    for (int kc = 0; kc < nK; kc++) {
        if (kc + 1 < nK) cp_wait<1>(); else cp_wait<0>();
        __syncthreads();
        if (kc + 2 < nK) load_stage(kc + 2);

        const uint32_t sa = sb + (kc % STAGES) * STG_BYTES;
        const uint32_t sbs = sa + 16384;

#pragma unroll
        for (int k16 = 0; k16 < 4; k16++) {
            uint32_t af[2][4];
#pragma unroll
            for (int mi = 0; mi < 2; mi++)
                ldm4(af[mi], sa + swz128(((a_row + mi * 16) << 7) + k16 * 32 + a_colb));
#pragma unroll
            for (int nj = 0; nj < 4; nj++) {
                uint32_t bf[4];
                ldm4(bf, sbs + swz128(((b_row + nj * 16) << 7) + k16 * 32 + b_colb));
#pragma unroll
                for (int mi = 0; mi < 2; mi++) {
                    mma16816(acc[mi][2 * nj],     af[mi], bf[0], bf[1]);
                    mma16816(acc[mi][2 * nj + 1], af[mi], bf[2], bf[3]);
                }
            }
        }
    }

    const int g = lane >> 2, t = lane & 3;
    if (outS2) {
        const int half_ = N >> 1;
#pragma unroll
        for (int mi = 0; mi < 2; mi++) {
#pragma unroll
            for (int ni = 0; ni < 8; ni++) {
                const int col = n0 + wn + ni * 8 + 2 * t;
                __half* base = outS;
                int c2 = col;
                if (col >= half_) { base = outS2; c2 = col - half_; }
#pragma unroll
                for (int rr = 0; rr < 2; rr++) {
                    const int row = m0 + wm + mi * 16 + g + rr * 8;
                    *(uint32_t*)&base[(size_t)row * half_ + c2] =
                        pk2h(acc[mi][ni][2 * rr], acc[mi][ni][2 * rr + 1]);
                }
            }
        }
    } else if (outS) {
#pragma unroll
        for (int mi = 0; mi < 2; mi++) {
#pragma unroll
            for (int ni = 0; ni < 8; ni++) {
                const int col = n0 + wn + ni * 8 + 2 * t;
#pragma unroll
                for (int rr = 0; rr < 2; rr++) {
                    const int row = m0 + wm + mi * 16 + g + rr * 8;
                    *(uint32_t*)&outS[(size_t)row * N + col] =
                        pk2h(acc[mi][ni][2 * rr] * scale, acc[mi][ni][2 * rr + 1] * scale);
                }
            }
        }
    } else {
#pragma unroll
        for (int mi = 0; mi < 2; mi++) {
#pragma unroll
            for (int ni = 0; ni < 8; ni++) {
                const int row = m0 + wm + mi * 16 + g;
                const int col = n0 + wn + ni * 8 + 2 * t;
                float b0 = bias[col], b1 = bias[col + 1];
                float2 v0 = make_float2(acc[mi][ni][0] + b0, acc[mi][ni][1] + b1);
                float2 v1 = make_float2(acc[mi][ni][2] + b0, acc[mi][ni][3] + b1);
                *(float2*)&C[(size_t)row * N + col] = v0;
                *(float2*)&C[(size_t)(row + 8) * N + col] = v1;
            }
        }
    }
}

// ---------------------------------------------------------------------------
// Attention core (bit-identical math since R11).
// ---------------------------------------------------------------------------
__device__ __forceinline__ void attn_core(
    const __half* __restrict__ Qs, const __half* __restrict__ Ks,
    const __half* __restrict__ Vs, __half* __restrict__ AH,
    int b, int h, int q0, char* smem)
{
    const uint32_t Qb = smem_u32(smem);
    const uint32_t KVb = Qb + 16384;
    const int tid = threadIdx.x;
    const int lane = tid & 31;
    const int wid = tid >> 5;

    const __half* Qg = Qs + ((size_t)(b * SQ + q0)) * INNER + h * 64;
    const __half* Kg = Ks + ((size_t)(b * SKV)) * INNER + h * 64;
    const __half* Vg = Vs + ((size_t)(b * SKV)) * INNER + h * 64;

#pragma unroll
    for (int i = 0; i < 4; i++) {
        int cid = (i << 8) + tid;
        int r = cid >> 3, w = cid & 7;
        uint32_t dst = Qb + (r << 7) + ((w << 4) ^ ((r & 7) << 4));
        cp16(dst, Qg + (size_t)r * INNER + w * 8);
    }
    cp_commit();

    auto load_kv = [&](int c) {
        const uint32_t st = KVb + (c & 1) * 16384;
#pragma unroll
        for (int i = 0; i < 4; i++) {
            int cid = (i << 8) + tid;
            int isV = cid >> 9;
            int l9 = cid & 511;
            int r = l9 >> 3, w = l9 & 7;
            const __half* src = (isV ? Vg : Kg) + (size_t)(c * 64 + r) * INNER + w * 8;
            uint32_t dst = st + isV * 8192 + (r << 7) + ((w << 4) ^ ((r & 7) << 4));
            cp16(dst, src);
        }
        cp_commit();
    };
    load_kv(0);
    load_kv(1);

    const int wm = wid << 4;
    const uint32_t a_row = wm + (lane & 15);
    const uint32_t a_csel = (lane >> 4) << 4;
    const int q2 = lane >> 3;
    const uint32_t b_roff = ((q2 >> 1) << 3) + (lane & 7);
    const uint32_t b_csel = (q2 & 1) << 4;
    const uint32_t v_roff = (((lane >> 3) & 1) << 3) + (lane & 7);
    const uint32_t v_csel = (lane >> 4) << 4;

    float o[8][4];
#pragma unroll
    for (int ni = 0; ni < 8; ni++)
#pragma unroll
        for (int j = 0; j < 4; j++) o[ni][j] = 0.f;
    float lacc[4] = {0.f, 0.f, 0.f, 0.f};

    for (int kc = 0; kc < SKV / 64; kc++) {
        if (kc + 1 < SKV / 64) cp_wait<1>(); else cp_wait<0>();
        __syncthreads();
        const uint32_t Kst = KVb + (kc & 1) * 16384;
        const uint32_t Vst = Kst + 8192;

        float s[8][4];
#pragma unroll
        for (int ni = 0; ni < 8; ni++)
#pragma unroll
            for (int j = 0; j < 4; j++) s[ni][j] = 0.f;

#pragma unroll
        for (int k16 = 0; k16 < 4; k16++) {
            uint32_t af[4];
            ldm4(af, Qb + swz128((a_row << 7) + k16 * 32 + a_csel));
#pragma unroll
            for (int nj = 0; nj < 4; nj++) {
                const uint32_t br = nj * 16 + b_roff;
                uint32_t bf[4];
                ldm4(bf, Kst + swz128((br << 7) + k16 * 32 + b_csel));
                mma16816(s[2 * nj],     af, bf[0], bf[1]);
                mma16816(s[2 * nj + 1], af, bf[2], bf[3]);
            }
        }

        uint32_t pf[4][4];
#pragma unroll
        for (int nj = 0; nj < 4; nj++) {
            pf[nj][0] = ex2h2(pk2h(s[2 * nj][0],     s[2 * nj][1]));
            pf[nj][1] = ex2h2(pk2h(s[2 * nj][2],     s[2 * nj][3]));
            pf[nj][2] = ex2h2(pk2h(s[2 * nj + 1][0], s[2 * nj + 1][1]));
            pf[nj][3] = ex2h2(pk2h(s[2 * nj + 1][2], s[2 * nj + 1][3]));
            mma16816(lacc, pf[nj], ONESH2, ONESH2);
        }

#pragma unroll
        for (int j = 0; j < 4; j++) {
            const uint32_t vr = j * 16 + v_roff;
#pragma unroll
            for (int u = 0; u < 4; u++) {
                uint32_t vf[4];
                ldm4t(vf, Vst + swz128((vr << 7) + u * 32 + v_csel));
                mma16816(o[2 * u],     pf[j], vf[0], vf[1]);
                mma16816(o[2 * u + 1], pf[j], vf[2], vf[3]);
            }
        }

        __syncthreads();
        if (kc + 2 < SKV / 64) load_kv(kc + 2);
    }

    const float inv0 = 1.f / lacc[0], inv1 = 1.f / lacc[2];

    const int r0 = q0 + wm + (lane >> 2);
    __half* base0 = AH + (size_t)(b * SQ + r0) * INNER + h * 64;
    __half* base1 = base0 + (size_t)8 * INNER;
#pragma unroll
    for (int ni = 0; ni < 8; ni++) {
        const int dd = ni * 8 + 2 * (lane & 3);
        *(uint32_t*)(base0 + dd) = pk2h(o[ni][0] * inv0, o[ni][1] * inv0);
        *(uint32_t*)(base1 + dd) = pk2h(o[ni][2] * inv1, o[ni][3] * inv1);
    }
}

// ---------------------------------------------------------------------------
// Tiny reset kernel (1 block) — runs before the fused kernel each replay.
// ---------------------------------------------------------------------------
__global__ void reset_counters()
{
    int t = threadIdx.x;
    if (t == 0) { g_wq = 0; g_wkv = 0; }
    if (t < BMAX) g_kv[t] = 0;
    if (t < NCB) g_cc[t] = 0;
    if (t < NRB) { g_xc[t] = 0; g_attn[t] = 0; }
    for (int i = t; i < NRB * 4; i += 256) g_qflag[i] = 0;
}

// ---------------------------------------------------------------------------
// Single fused kernel, static blockIdx order (topological):
//   [x-conv | ctx-conv | w-transpose | Q tiles | KV tiles | attn (b,qx,h) | O]
// Every wait targets strictly earlier blocks -> deadlock-free under in-order
// CLC dispatch. Attention for batch b starts as soon as its KV tiles (earliest
// in the KV range) and Q row-block are done, filling the QKV tail.
// ---------------------------------------------------------------------------
__global__ __launch_bounds__(256, 2)
void fused_all(const float* __restrict__ X, const float* __restrict__ Ctx,
               const float* __restrict__ Wq, const float* __restrict__ Wk,
               const float* __restrict__ Wv, const float* __restrict__ Wo,
               const float* __restrict__ bo, float* __restrict__ out, int B)
{
    extern __shared__ char smem[];
    const int tid = threadIdx.x;
    const int w = blockIdx.x;

    __half *qs = g_qs, *ks = g_ks, *vs = g_vs, *xh = g_xh, *ch = g_ch, *ah = g_ah;
    __half *wqh = g_wqh, *wkvh = g_wkvh, *woh = g_woh;

    const int nX = B * SQ / 128;            // 128
    const int nC = B * SKV / 128;           // 32
    const int cConv = nX + nC + 1792;       // 1952
    const int nQ = 4 * (B * SQ / 128);      // 512
    const int cQ = cConv + nQ;
    const int nKV = 8 * (B * SKV / 128);    // 256
    const int cKV = cQ + nKV;
    const int nAtt = B << 8;                // 1024
    const int cAtt = cKV + nAtt;
    const float qscale = 0.125f * 1.44269504f;

    if (w < nX) {
        // ---- x convert: row-block w (128 rows x 1024) ----
        long base = (long)w << 15;
#pragma unroll 8
        for (int i = 0; i < 128; i++) {
            long idx = base + tid + (i << 8);
            float4 v = ((const float4*)X)[idx];
            __half hv[4];
            hv[0] = __float2half(v.x); hv[1] = __float2half(v.y);
            hv[2] = __float2half(v.z); hv[3] = __float2half(v.w);
            ((uint2*)xh)[idx] = *(uint2*)hv;
        }
        __syncthreads();
        if (tid == 0) red_rel(&g_xc[w], 1);
        return;
    }
    if (w < nX + nC) {
        // ---- ctx convert: row-block c (128 rows x 768) ----
        const int c = w - nX;
        long base = (long)c * 24576;
#pragma unroll 8
        for (int i = 0; i < 96; i++) {
            long idx = base + tid + (i << 8);
            float4 v = ((const float4*)Ctx)[idx];
            __half hv[4];
            hv[0] = __float2half(v.x); hv[1] = __float2half(v.y);
            hv[2] = __float2half(v.z); hv[3] = __float2half(v.w);
            ((uint2*)ch)[idx] = *(uint2*)hv;
        }
        __syncthreads();
        if (tid == 0) red_rel(&g_cc[c], 1);
        return;
    }
    if (w < cConv) {
        // ---- weight transpose item ----
        int bid = w - nX - nC;
        const int cls = (bid < 512) ? 0 : (bid < 1280 ? 1 : 2);
        const float* W;
        __half* Wt;
        int K, N, nx;
        if (bid < 512)       { W = Wq; Wt = wqh;  K = QD;   N = INNER; nx = 16; }
        else if (bid < 896)  { bid -= 512;  W = Wk; Wt = wkvh; K = CD; N = INNER; nx = 16; }
        else if (bid < 1280) { bid -= 896;  W = Wv; Wt = wkvh + (size_t)INNER * CD; K = CD; N = INNER; nx = 16; }
        else                 { bid -= 1280; W = Wo; Wt = woh;  K = INNER; N = QD;  nx = 32; }
        const int n0 = (bid % nx) << 5, k0 = (bid / nx) << 5;
        float* t = (float*)smem;
        const int tx = tid & 31, ty = tid >> 5;
#pragma unroll
        for (int i = 0; i < 4; i++)
            t[(ty + 8 * i) * 33 + tx] = W[(size_t)(k0 + ty + 8 * i) * N + n0 + tx];
        __syncthreads();
#pragma unroll
        for (int i = 0; i < 4; i++) {
            const int n = n0 + ty + 8 * i;
            const int k = k0 + tx;
            Wt[(size_t)n * K + k] = __float2half(t[tx * 33 + ty + 8 * i]);
        }
        __syncthreads();
        if (tid == 0) {
            if (cls == 0) red_rel(&g_wq, 1);
            else if (cls == 1) red_rel(&g_wkv, 1);
        }
        return;
    }
    if (w < cQ) {
        // ---- Q projection tile ----
        const int i = w - cConv;
        const int by = i >> 2, bx = i & 3;
        wait_ge(&g_wq, 512);
        wait_ge(&g_xc[by], 1);
        gemm_core(xh, wqh, nullptr, nullptr, qs, nullptr, qscale,
                  INNER, QD, bx, by, smem);
        __syncthreads();
        if (tid == 0) red_rel(&g_qflag[i], 1);      // [by*4 + bx]
        return;
    }
    if (w < cKV) {
        // ---- KV projection tile ----
        const int j = w - cQ;
        const int by = j >> 3, bx = j & 7;
        wait_ge(&g_wkv, 768);
        wait_ge(&g_cc[by], 1);
        gemm_core(ch, wkvh, nullptr, nullptr, ks, vs, 1.0f,
                  2 * INNER, CD, bx, by, smem);
        __syncthreads();
        if (tid == 0) red_rel(&g_kv[by >> 3], 1);
        return;
    }
    if (w < cAtt) {
        // ---- attention tile, order (b, qx, h) ----
        const int a = w - cKV;
        const int b = a >> 8;
        const int r = a & 255;
        const int qx = r >> 3;
        const int h = r & 7;
        const int rb = b * 32 + qx;
        wait_ge(&g_kv[b], 64);
        wait_ge(&g_qflag[rb * 4 + (h >> 1)], 1);
        attn_core(qs, ks, vs, ah, b, h, qx << 7, smem);
        __syncthreads();
        if (tid == 0) red_rel(&g_attn[rb], 1);
        return;
    }
    // ---- O projection tile, rb-major ----
    const int o = w - cAtt;
    const int by = o >> 3;
    const int bx = o & 7;
    wait_ge(&g_attn[by], 8);
    gemm_core(ah, woh, out, bo, nullptr, nullptr, 1.0f,
              QD, INNER, bx, by, smem);
}

// ---------------------------------------------------------------------------
extern "C" void kernel_launch(void* const* d_in, const int* in_sizes, int n_in,
                              void* d_out, int out_size)
{
    const float* x   = (const float*)d_in[0];
    const float* ctx = (const float*)d_in[1];
    const float* Wq  = (const float*)d_in[2];
    const float* Wk  = (const float*)d_in[3];
    const float* Wv  = (const float*)d_in[4];
    const float* Wo  = (const float*)d_in[5];
    const float* bo  = (const float*)d_in[6];
    float* out = (float*)d_out;

    const int B = in_sizes[0] / (SQ * QD);

    cudaFuncSetAttribute(fused_all, cudaFuncAttributeMaxDynamicSharedMemorySize, GEMM_SMEM);

    const int nX = B * SQ / 128;
    const int nC = B * SKV / 128;
    const int nQ = 4 * (B * SQ / 128);
    const int nKV = 8 * (B * SKV / 128);
    const int nAtt = B * 256;
    const int nO = 8 * (B * SQ / 128);
    const int grid = nX + nC + 1792 + nQ + nKV + nAtt + nO;

    reset_counters<<<1, 256>>>();
    fused_all<<<grid, 256, GEMM_SMEM>>>(x, ctx, Wq, Wk, Wv, Wo, bo, out, B);
}